// round 12
// baseline (speedup 1.0000x reference)
#include <cuda_runtime.h>
#include <cuda_fp16.h>
#include <cstdint>

// ---------------- problem constants ----------------
constexpr int BATCH = 32768;
constexpr int NC    = 3648;     // combined features = 57*64 exactly (GEMM2 K)
constexpr int H1    = 512;
constexpr int H2    = 128;
constexpr int NA    = 4;

// ---------------- scratch (device globals; no allocation) ----------------
__device__ __align__(256) __half g_XP  [(size_t)BATCH * 256];     // position-major input
__device__ __align__(256) __half g_Wc  [7 * 64 * 64];             // per-conv weight tiles
__device__ __align__(256) __half g_comb[(size_t)BATCH * NC];      // 227 MB
__device__ __align__(256) __half g_fw0h[(size_t)H1 * NC];         // permuted fc0 weights
__device__ __align__(256) __half g_h1  [(size_t)BATCH * H1];
__device__ __align__(256) __half g_fw1h[(size_t)H2 * H1];

// conv geometry tables
__constant__ int c_off[7] = {0, 768, 1536, 2048, 2560, 2816, 3072};
__constant__ int c_P[7]   = {12, 12, 8, 8, 4, 4, 9};
__constant__ int c_kh[7]  = {1, 2, 1, 3, 1, 4, 2};
__constant__ int c_kw[7]  = {2, 1, 3, 1, 4, 1, 2};

struct ConvPtrs { const float* w[7]; const float* b[7]; };

// ---------------- prep: XP transpose-convert, COALESCED (launch idx 0) ----------------
__global__ void __launch_bounds__(256)
k_xp(const float* __restrict__ x) {
    __shared__ float sx[8][256];
    int s0 = blockIdx.x * 8;
    const float* src = x + (size_t)s0 * 256;
#pragma unroll
    for (int s = 0; s < 8; s++)
        sx[s][threadIdx.x] = src[s * 256 + threadIdx.x];
    __syncthreads();
    int t = threadIdx.x;
    int si = ((t & 15) << 4) | (t >> 4);      // XP[pos*16+c] = x[c*16+pos]
    __half* dst = g_XP + (size_t)s0 * 256;
#pragma unroll
    for (int s = 0; s < 8; s++)
        dst[s * 256 + t] = __float2half_rn(sx[s][si]);
}

// ---------------- prep: Wc tiles + fw1 convert + fw0 permute (launch idx 1) ----------------
constexpr int PERM_BLOCKS = (H1 * NC + 255) / 256;   // 7296
__global__ void __launch_bounds__(256)
k_prep(const float* __restrict__ fw0, const float* __restrict__ fw1, ConvPtrs cp) {
    int bid = blockIdx.x;
    if (bid < PERM_BLOCKS) {
        int t = bid * 256 + threadIdx.x;
        if (t >= H1 * NC) return;
        int j = t / NC, cc = t - j * NC;
        int ci = 0;
#pragma unroll
        for (int q = 1; q < 7; q++) if (cc >= c_off[q]) ci = q;
        int local = cc - c_off[ci];
        int p = local >> 6, o = local & 63;
        g_fw0h[t] = __float2half_rn(fw0[j * NC + c_off[ci] + o * c_P[ci] + p]);
    } else if (bid < PERM_BLOCKS + 7) {
        int ci = bid - PERM_BLOCKS;
        int o = threadIdx.x;
        if (o >= 64) return;
        int kh = c_kh[ci], kw = c_kw[ci];
        int ks = kh * kw;
        __half* dst = g_Wc + ci * 4096 + o * 64;
        for (int k = 0; k < 64; k++) dst[k] = __half(0.0f);
        const float* w = cp.w[ci] + o * 16 * ks;
        for (int i = 0; i < ks; i++)
            for (int c = 0; c < 16; c++)
                dst[i * 16 + c] = __float2half_rn(w[c * ks + i]);
    } else {
        int i = (bid - PERM_BLOCKS - 7) * 256 + threadIdx.x;
        if (i >= H2 * H1 / 8) return;
        const float4* s = (const float4*)fw1 + 2 * (size_t)i;
        float4 a = s[0], b = s[1];
        __half2 h0 = __floats2half2_rn(a.x, a.y);
        __half2 h1 = __floats2half2_rn(a.z, a.w);
        __half2 h2 = __floats2half2_rn(b.x, b.y);
        __half2 h3 = __floats2half2_rn(b.z, b.w);
        uint4 o;
        o.x = *(uint32_t*)&h0; o.y = *(uint32_t*)&h1;
        o.z = *(uint32_t*)&h2; o.w = *(uint32_t*)&h3;
        ((uint4*)g_fw1h)[i] = o;
    }
}

// ---------------- GEMM helpers ----------------
__device__ __forceinline__ uint32_t swz(uint32_t x) { return x ^ ((x >> 3) & 0x70); }

__device__ __forceinline__ void cp16(uint32_t saddr, const void* g) {
    asm volatile("cp.async.cg.shared.global [%0], [%1], 16;\n" :: "r"(saddr), "l"(g) : "memory");
}
__device__ __forceinline__ void cp_commit() {
    asm volatile("cp.async.commit_group;\n" ::: "memory");
}
template <int N>
__device__ __forceinline__ void cp_wait() {
    asm volatile("cp.async.wait_group %0;\n" :: "n"(N) : "memory");
}

__device__ __forceinline__ void ldsm4(uint32_t& r0, uint32_t& r1, uint32_t& r2, uint32_t& r3,
                                      uint32_t addr) {
    asm volatile("ldmatrix.sync.aligned.m8n8.x4.shared.b16 {%0,%1,%2,%3}, [%4];"
                 : "=r"(r0), "=r"(r1), "=r"(r2), "=r"(r3) : "r"(addr));
}

__device__ __forceinline__ void mma16816(float c[4], const uint32_t a[4], const uint32_t b[2]) {
    asm volatile(
        "mma.sync.aligned.m16n8k16.row.col.f32.f16.f16.f32 "
        "{%0,%1,%2,%3}, {%4,%5,%6,%7}, {%8,%9}, {%0,%1,%2,%3};"
        : "+f"(c[0]), "+f"(c[1]), "+f"(c[2]), "+f"(c[3])
        : "r"(a[0]), "r"(a[1]), "r"(a[2]), "r"(a[3]), "r"(b[0]), "r"(b[1]));
}

// ---------------- direct conv tile (device) — unchanged (R9-passing) ----------------
template <int P, int OW, int KH, int KW>
__device__ __forceinline__ void conv_tile(int tile, int BASE, const __half* __restrict__ wc,
                                          const float* __restrict__ bias) {
    constexpr int NS  = KH * KW;
    constexpr int SMX = 128 / P + 2;

    extern __shared__ char sm[];
    uint32_t sX = (uint32_t)__cvta_generic_to_shared(sm);
    uint32_t sB = (sX + SMX * 544 + 127) & ~127u;
    uint32_t sO = sX;

    const int tid  = threadIdx.x;
    const int lane = tid & 31;
    const int w    = tid >> 5;
    const int wm   = w & 3;
    const int wn   = w >> 2;

    const int R0    = tile * 128;
    const int b0    = R0 / P;
    const int bLast = (R0 + 127) / P;
    const int scnt  = bLast - b0 + 1;

    for (int ch = tid; ch < scnt * 32; ch += 256) {
        int s = ch >> 5, j = ch & 31;
        int pos = j >> 1, hf = j & 1;
        uint32_t off = ((uint32_t)(pos * 32 + hf * 16)) ^ (uint32_t)((pos & 4) << 2);
        cp16(sX + s * 544 + off, g_XP + ((size_t)(b0 + s) << 8) + pos * 16 + hf * 8);
    }
    for (int ch = tid; ch < 512; ch += 256) {
        int row = ch >> 3, cc = ch & 7;
        cp16(sB + swz((uint32_t)(row * 128 + cc * 16)), wc + row * 64 + cc * 8);
    }
    cp_commit();
    cp_wait<0>();
    __syncthreads();

    uint32_t rowaddr[2];
    int wpos0[2];
#pragma unroll
    for (int mt = 0; mt < 2; mt++) {
        int r = R0 + wm * 32 + mt * 16 + (lane & 15);
        int b = r / P, p = r - b * P;
        int py = p / OW, px = p - py * OW;
        rowaddr[mt] = sX + (b - b0) * 544;
        wpos0[mt]   = py * 4 + px;
    }

    float acc[2][4][4];
#pragma unroll
    for (int i = 0; i < 2; i++)
#pragma unroll
        for (int j = 0; j < 4; j++)
#pragma unroll
            for (int q = 0; q < 4; q++) acc[i][j][q] = 0.0f;

#pragma unroll
    for (int i = 0; i < NS; i++) {
        const int D = (i / KW) * 4 + (i % KW);
        uint32_t af[2][4];
#pragma unroll
        for (int mt = 0; mt < 2; mt++) {
            int wp = wpos0[mt] + D;
            uint32_t off = ((uint32_t)(wp * 32 + ((lane >> 4) << 4))) ^ (uint32_t)((wp & 4) << 2);
            ldsm4(af[mt][0], af[mt][1], af[mt][2], af[mt][3], rowaddr[mt] + off);
        }
        uint32_t bf[4][2];
#pragma unroll
        for (int nt2 = 0; nt2 < 2; nt2++) {
            int brow = wn * 32 + nt2 * 16 + ((lane & 16) >> 1) + (lane & 7);
            uint32_t off = swz((uint32_t)(brow * 128 + i * 32 + (((lane >> 3) & 1) << 4)));
            uint32_t r0, r1, r2, r3;
            ldsm4(r0, r1, r2, r3, sB + off);
            bf[nt2 * 2][0] = r0;     bf[nt2 * 2][1] = r1;
            bf[nt2 * 2 + 1][0] = r2; bf[nt2 * 2 + 1][1] = r3;
        }
#pragma unroll
        for (int mt = 0; mt < 2; mt++)
#pragma unroll
            for (int nt = 0; nt < 4; nt++) mma16816(acc[mt][nt], af[mt], bf[nt]);
    }

    __syncthreads();
#pragma unroll
    for (int mt = 0; mt < 2; mt++) {
#pragma unroll
        for (int sub = 0; sub < 2; sub++) {
            int row = wm * 32 + mt * 16 + sub * 8 + (lane >> 2);
#pragma unroll
            for (int nt = 0; nt < 4; nt++) {
                int o = wn * 32 + nt * 8 + ((lane & 3) << 1);
                float2 bb = *(const float2*)(bias + o);
                float v0 = fmaxf(acc[mt][nt][sub * 2 + 0] + bb.x, 0.0f);
                float v1 = fmaxf(acc[mt][nt][sub * 2 + 1] + bb.y, 0.0f);
                __half2 hv = __floats2half2_rn(v0, v1);
                asm volatile("st.shared.b32 [%0], %1;"
                             :: "r"(sO + row * 144 + o * 2), "r"(*(uint32_t*)&hv) : "memory");
            }
        }
    }
    __syncthreads();

    for (int ch = tid; ch < 1024; ch += 256) {
        int row = ch >> 3, w8 = ch & 7;
        int r = R0 + row;
        int b = r / P, p = r - b * P;
        uint4 v;
        asm volatile("ld.shared.v4.u32 {%0,%1,%2,%3}, [%4];"
                     : "=r"(v.x), "=r"(v.y), "=r"(v.z), "=r"(v.w)
                     : "r"(sO + row * 144 + w8 * 16));
        *(uint4*)(g_comb + (size_t)b * NC + BASE + p * 64 + w8 * 8) = v;
    }
}

// single launch for all 7 convs (launch idx 2)
__global__ void __launch_bounds__(256, 3)
conv_all(ConvPtrs cp) {
    int bid = blockIdx.x;
    if (bid < 3072)       conv_tile<12, 3, 1, 2>(bid,         0,    g_Wc,          cp.b[0]);
    else if (bid < 6144)  conv_tile<12, 4, 2, 1>(bid - 3072,  768,  g_Wc + 4096,   cp.b[1]);
    else if (bid < 8192)  conv_tile<8, 2, 1, 3> (bid - 6144,  1536, g_Wc + 8192,   cp.b[2]);
    else if (bid < 10240) conv_tile<8, 4, 3, 1> (bid - 8192,  2048, g_Wc + 12288,  cp.b[3]);
    else if (bid < 11264) conv_tile<4, 1, 1, 4> (bid - 10240, 2560, g_Wc + 16384,  cp.b[4]);
    else if (bid < 12288) conv_tile<4, 4, 4, 1> (bid - 11264, 2816, g_Wc + 20480,  cp.b[5]);
    else                  conv_tile<9, 3, 2, 2> (bid - 12288, 3072, g_Wc + 24576,  cp.b[6]);
}

// ---------------- dense GEMM (NT), fragment double-buffered, FIXED addressing ----------
// (launch idx 3 — PROFILED) BM=128, BN=128, BK=64, 3-stage cp.async, 256 threads,
// warp tile 32x64, 2 CTAs/SM. swz computed on (pre + ks*32) — no linear-swizzle carry bug.
__global__ void __launch_bounds__(256, 2)
gemm_nt(const __half* __restrict__ A, const __half* __restrict__ Bw,
        const float* __restrict__ bias, __half* __restrict__ C, int N, int K) {
    constexpr int STAGE = 128 * 128 * 2;
    constexpr int MT = 2, NT = 8;

    extern __shared__ char smemraw[];
    uint32_t sbase = (uint32_t)__cvta_generic_to_shared(smemraw);

    const int tid  = threadIdx.x;
    const int lane = tid & 31;
    const int w    = tid >> 5;
    const int wm   = w & 3;
    const int wn   = w >> 2;
    const int bm   = blockIdx.y, bn = blockIdx.x;

    const __half* Ab = A  + (size_t)bm * 128 * K;
    const __half* Bb = Bw + (size_t)bn * 128 * K;
    const int nk = K >> 6;

    // UNSWIZZLED per-warp fragment bases (swizzle applied per use, after +ks*32)
    uint32_t preA[MT], preB[NT / 2];
#pragma unroll
    for (int mt = 0; mt < MT; mt++)
        preA[mt] = (uint32_t)((wm * 32 + mt * 16 + (lane & 15)) * 128 + ((lane >> 4) << 4));
#pragma unroll
    for (int nt2 = 0; nt2 < NT / 2; nt2++) {
        int brow = wn * 64 + nt2 * 16 + ((lane & 16) >> 1) + (lane & 7);
        preB[nt2] = (uint32_t)(brow * 128 + (((lane >> 3) & 1) << 4));
    }

    float acc[MT][NT][4];
#pragma unroll
    for (int i = 0; i < MT; i++)
#pragma unroll
        for (int j = 0; j < NT; j++)
#pragma unroll
            for (int q = 0; q < 4; q++) acc[i][j][q] = 0.0f;

    auto load_stage = [&](int kt, int s) {
        int k0 = kt << 6;
        uint32_t sA = sbase + s * STAGE;
        uint32_t sB = sA + 128 * 128;
#pragma unroll
        for (int c = tid; c < 128 * 8; c += 256) {
            int row = c >> 3, cc = c & 7;
            cp16(sA + swz((uint32_t)(row * 128 + cc * 16)),
                 Ab + (size_t)row * K + k0 + cc * 8);
        }
#pragma unroll
        for (int c = tid; c < 128 * 8; c += 256) {
            int row = c >> 3, cc = c & 7;
            cp16(sB + swz((uint32_t)(row * 128 + cc * 16)),
                 Bb + (size_t)row * K + k0 + cc * 8);
        }
        cp_commit();
    };

    uint32_t af[2][MT][4];
    uint32_t bf[2][NT][2];

    auto frag_load = [&](int b, uint32_t stg, int ks) {
        uint32_t d = (uint32_t)(ks * 32);
#pragma unroll
        for (int mt = 0; mt < MT; mt++)
            ldsm4(af[b][mt][0], af[b][mt][1], af[b][mt][2], af[b][mt][3],
                  stg + swz(preA[mt] + d));
#pragma unroll
        for (int nt2 = 0; nt2 < NT / 2; nt2++) {
            uint32_t r0, r1, r2, r3;
            ldsm4(r0, r1, r2, r3, stg + 16384u + swz(preB[nt2] + d));
            bf[b][nt2 * 2][0] = r0;     bf[b][nt2 * 2][1] = r1;
            bf[b][nt2 * 2 + 1][0] = r2; bf[b][nt2 * 2 + 1][1] = r3;
        }
    };
    auto do_mma = [&](int b) {
#pragma unroll
        for (int mt = 0; mt < MT; mt++)
#pragma unroll
            for (int nt = 0; nt < NT; nt++) mma16816(acc[mt][nt], af[b][mt], bf[b][nt]);
    };

    load_stage(0, 0);
    load_stage(1, 1);
    cp_wait<1>();
    __syncthreads();
    frag_load(0, sbase, 0);

    uint32_t stg = sbase;
#pragma unroll 1
    for (int kt = 0; kt < nk; ++kt) {
#pragma unroll
        for (int ks = 0; ks < 3; ++ks) {
            frag_load((ks + 1) & 1, stg, ks + 1);   // prefetch ks+1 frags
            do_mma(ks & 1);                          // compute ks
        }
        // ks == 3: cross the chunk boundary with next chunk's ks=0 frags prefetched
        uint32_t nstg = (stg == sbase + 2 * STAGE) ? sbase : stg + STAGE;
        if (kt + 1 < nk) {
            cp_wait<0>();            // stage kt+1 fully resident
            __syncthreads();         // old-stage reads drained before refill
            if (kt + 2 < nk) {
                int s = kt + 2; while (s >= 3) s -= 3;
                load_stage(kt + 2, s);
            }
            frag_load(0, nstg, 0);   // ks=0 of next chunk
        }
        do_mma(1);                   // compute ks=3
        stg = nstg;
    }

#pragma unroll
    for (int mt = 0; mt < MT; ++mt) {
        int r0 = bm * 128 + wm * 32 + mt * 16 + (lane >> 2);
#pragma unroll
        for (int nt = 0; nt < NT; ++nt) {
            int col = bn * 128 + wn * 64 + nt * 8 + ((lane & 3) << 1);
            float2 bb = *(const float2*)(bias + col);
            float v0 = fmaxf(acc[mt][nt][0] + bb.x, 0.0f);
            float v1 = fmaxf(acc[mt][nt][1] + bb.y, 0.0f);
            float v2 = fmaxf(acc[mt][nt][2] + bb.x, 0.0f);
            float v3 = fmaxf(acc[mt][nt][3] + bb.y, 0.0f);
            *(__half2*)(C + (size_t)r0 * N + col)       = __floats2half2_rn(v0, v1);
            *(__half2*)(C + (size_t)(r0 + 8) * N + col) = __floats2half2_rn(v2, v3);
        }
    }
}

// ---------------- GEMM3 fused with final FC (launch idx 4) — unchanged ----------------
__global__ void __launch_bounds__(256, 2)
gemm3_fused(const __half* __restrict__ A, const __half* __restrict__ Bw,
            const float* __restrict__ fb1, const float* __restrict__ fw2,
            const float* __restrict__ fb2, float* __restrict__ out) {
    constexpr int STAGES = 3;
    constexpr int STAGE  = 128 * 128 * 2;
    constexpr int MT = 2, NT = 8;
    constexpr int K = H1;
    constexpr int nk = K >> 6;   // 8

    extern __shared__ char smemraw[];
    uint32_t sbase = (uint32_t)__cvta_generic_to_shared(smemraw);

    const int tid  = threadIdx.x;
    const int lane = tid & 31;
    const int w    = tid >> 5;
    const int wm   = w & 3;
    const int wn   = w >> 2;
    const int bm   = blockIdx.y;

    const __half* Ab = A + (size_t)bm * 128 * K;
    const __half* Bb = Bw;

    float acc[MT][NT][4];
#pragma unroll
    for (int i = 0; i < MT; i++)
#pragma unroll
        for (int j = 0; j < NT; j++)
#pragma unroll
            for (int q = 0; q < 4; q++) acc[i][j][q] = 0.0f;

    auto load_stage = [&](int kt, int s) {
        int k0 = kt << 6;
        uint32_t sA = sbase + s * STAGE;
        uint32_t sB = sA + 128 * 128;
#pragma unroll
        for (int c = tid; c < 128 * 8; c += 256) {
            int row = c >> 3, cc = c & 7;
            cp16(sA + swz((uint32_t)(row * 128 + cc * 16)),
                 Ab + (size_t)row * K + k0 + cc * 8);
        }
#pragma unroll
        for (int c = tid; c < 128 * 8; c += 256) {
            int row = c >> 3, cc = c & 7;
            cp16(sB + swz((uint32_t)(row * 128 + cc * 16)),
                 Bb + (size_t)row * K + k0 + cc * 8);
        }
        cp_commit();
    };

    load_stage(0, 0);
    load_stage(1, 1);

#pragma unroll 1
    for (int kt = 0; kt < nk; ++kt) {
        if (kt == nk - 1) cp_wait<0>(); else cp_wait<1>();
        __syncthreads();
        if (kt + 2 < nk) {
            int s = kt + 2; while (s >= STAGES) s -= STAGES;
            load_stage(kt + 2, s);
        }
        int cs = kt; while (cs >= STAGES) cs -= STAGES;
        uint32_t aT = sbase + cs * STAGE;
        uint32_t bT = aT + 128 * 128;

#pragma unroll
        for (int ks = 0; ks < 4; ++ks) {
            uint32_t af[MT][4];
#pragma unroll
            for (int mt = 0; mt < MT; ++mt) {
                uint32_t off = swz((uint32_t)((wm * 32 + mt * 16 + (lane & 15)) * 128 +
                                              ks * 32 + ((lane >> 4) << 4)));
                ldsm4(af[mt][0], af[mt][1], af[mt][2], af[mt][3], aT + off);
            }
            uint32_t bf[NT][2];
#pragma unroll
            for (int nt2 = 0; nt2 < NT / 2; ++nt2) {
                int brow = wn * 64 + nt2 * 16 + ((lane & 16) >> 1) + (lane & 7);
                uint32_t off = swz((uint32_t)(brow * 128 + ks * 32 + (((lane >> 3) & 1) << 4)));
                uint32_t r0, r1, r2, r3;
                ldsm4(r0, r1, r2, r3, bT + off);
                bf[nt2 * 2][0] = r0;     bf[nt2 * 2][1] = r1;
                bf[nt2 * 2 + 1][0] = r2; bf[nt2 * 2 + 1][1] = r3;
            }
#pragma unroll
            for (int mt = 0; mt < MT; ++mt)
#pragma unroll
                for (int nt = 0; nt < NT; ++nt) mma16816(acc[mt][nt], af[mt], bf[nt]);
        }
    }

    __syncthreads();
    float* sfw2 = (float*)smemraw;         // [4][128]
    float* sout = sfw2 + 512;              // [128][4][2]
    for (int i = tid; i < 512; i += 256) sfw2[i] = fw2[i];
    __syncthreads();

#pragma unroll
    for (int mt = 0; mt < MT; ++mt) {
#pragma unroll
        for (int sub = 0; sub < 2; ++sub) {
            float p0 = 0.f, p1 = 0.f, p2 = 0.f, p3 = 0.f;
#pragma unroll
            for (int nt = 0; nt < NT; ++nt) {
                int coll = wn * 64 + nt * 8 + ((lane & 3) << 1);
                float v0 = fmaxf(acc[mt][nt][sub * 2 + 0] + __ldg(fb1 + coll), 0.0f);
                float v1 = fmaxf(acc[mt][nt][sub * 2 + 1] + __ldg(fb1 + coll + 1), 0.0f);
                p0 += v0 * sfw2[0 * 128 + coll] + v1 * sfw2[0 * 128 + coll + 1];
                p1 += v0 * sfw2[1 * 128 + coll] + v1 * sfw2[1 * 128 + coll + 1];
                p2 += v0 * sfw2[2 * 128 + coll] + v1 * sfw2[2 * 128 + coll + 1];
                p3 += v0 * sfw2[3 * 128 + coll] + v1 * sfw2[3 * 128 + coll + 1];
            }
#pragma unroll
            for (int d = 1; d <= 2; d <<= 1) {
                p0 += __shfl_xor_sync(0xffffffffu, p0, d);
                p1 += __shfl_xor_sync(0xffffffffu, p1, d);
                p2 += __shfl_xor_sync(0xffffffffu, p2, d);
                p3 += __shfl_xor_sync(0xffffffffu, p3, d);
            }
            if ((lane & 3) == 0) {
                int row = wm * 32 + mt * 16 + sub * 8 + (lane >> 2);
                sout[(row * 4 + 0) * 2 + wn] = p0;
                sout[(row * 4 + 1) * 2 + wn] = p1;
                sout[(row * 4 + 2) * 2 + wn] = p2;
                sout[(row * 4 + 3) * 2 + wn] = p3;
            }
        }
    }
    __syncthreads();
    for (int i = tid; i < 512; i += 256) {
        int row = i >> 2, j = i & 3;
        out[((size_t)(bm * 128 + row)) * NA + j] = sout[i * 2] + sout[i * 2 + 1] + __ldg(fb2 + j);
    }
}

// ---------------- launch ----------------
extern "C" void kernel_launch(void* const* d_in, const int* in_sizes, int n_in,
                              void* d_out, int out_size) {
    const float* x = (const float*)d_in[0];
    ConvPtrs cp;
    for (int i = 0; i < 7; i++) {
        cp.w[i] = (const float*)d_in[1 + 2 * i];
        cp.b[i] = (const float*)d_in[2 + 2 * i];
    }
    const float* fw0 = (const float*)d_in[15];
    const float* fb0 = (const float*)d_in[16];
    const float* fw1 = (const float*)d_in[17];
    const float* fb1 = (const float*)d_in[18];
    const float* fw2 = (const float*)d_in[19];
    const float* fb2 = (const float*)d_in[20];
    float* out = (float*)d_out;

    constexpr int SMEM_G = 3 * 128 * 128 * 2;  // 98304
    cudaFuncSetAttribute(gemm_nt,     cudaFuncAttributeMaxDynamicSharedMemorySize, SMEM_G);
    cudaFuncSetAttribute(gemm3_fused, cudaFuncAttributeMaxDynamicSharedMemorySize, SMEM_G);

    __half *comb, *fw0h, *h1, *fw1h;
    cudaGetSymbolAddress((void**)&comb, g_comb);
    cudaGetSymbolAddress((void**)&fw0h, g_fw0h);
    cudaGetSymbolAddress((void**)&h1,   g_h1);
    cudaGetSymbolAddress((void**)&fw1h, g_fw1h);

    // idx 0: XP transpose-convert (coalesced)
    k_xp<<<BATCH / 8, 256>>>(x);

    // idx 1: fused weight prep (fw0 permute, conv tiles, fw1 convert)
    k_prep<<<PERM_BLOCKS + 7 + 32, 256>>>(fw0, fw1, cp);

    // idx 2: all 7 convs -> comb
    conv_all<<<14592, 256, 27008>>>(cp);

    // idx 3: GEMM2  h1 = relu(comb * fw0h^T + fb0)   [32768, 512], K=3648  [PROFILED]
    {
        dim3 grid(H1 / 128, BATCH / 128);
        gemm_nt<<<grid, 256, SMEM_G>>>(comb, fw0h, fb0, h1, H1, NC);
    }
    // idx 4: GEMM3 + final FC fused
    {
        dim3 grid(1, BATCH / 128);
        gemm3_fused<<<grid, 256, SMEM_G>>>(h1, fw1h, fb1, fw2, fb2, out);
    }
}

// round 13
// speedup vs baseline: 1.0424x; 1.0424x over previous
#include <cuda_runtime.h>
#include <cuda_fp16.h>
#include <cstdint>

// ---------------- problem constants ----------------
constexpr int BATCH = 32768;
constexpr int NC    = 3648;     // combined features = 57*64 exactly (GEMM2 K)
constexpr int H1    = 512;
constexpr int H2    = 128;
constexpr int NA    = 4;

// ---------------- scratch (device globals; no allocation) ----------------
__device__ __align__(256) __half g_XP  [(size_t)BATCH * 256];     // position-major input
__device__ __align__(256) __half g_Wc  [7 * 64 * 64];             // per-conv weight tiles
__device__ __align__(256) __half g_comb[(size_t)BATCH * NC];      // 227 MB
__device__ __align__(256) __half g_fw0h[(size_t)H1 * NC];         // permuted fc0 weights
__device__ __align__(256) __half g_h1  [(size_t)BATCH * H1];
__device__ __align__(256) __half g_fw1h[(size_t)H2 * H1];

// conv geometry tables
__constant__ int c_off[7] = {0, 768, 1536, 2048, 2560, 2816, 3072};
__constant__ int c_P[7]   = {12, 12, 8, 8, 4, 4, 9};
__constant__ int c_kh[7]  = {1, 2, 1, 3, 1, 4, 2};
__constant__ int c_kw[7]  = {2, 1, 3, 1, 4, 1, 2};

struct ConvPtrs { const float* w[7]; const float* b[7]; };

// ---------------- prep: XP transpose-convert, COALESCED (launch idx 0) ----------------
__global__ void __launch_bounds__(256)
k_xp(const float* __restrict__ x) {
    __shared__ float sx[8][256];
    int s0 = blockIdx.x * 8;
    const float* src = x + (size_t)s0 * 256;
#pragma unroll
    for (int s = 0; s < 8; s++)
        sx[s][threadIdx.x] = src[s * 256 + threadIdx.x];
    __syncthreads();
    int t = threadIdx.x;
    int si = ((t & 15) << 4) | (t >> 4);      // XP[pos*16+c] = x[c*16+pos]
    __half* dst = g_XP + (size_t)s0 * 256;
#pragma unroll
    for (int s = 0; s < 8; s++)
        dst[s * 256 + t] = __float2half_rn(sx[s][si]);
}

// ---------------- prep: Wc tiles + fw1 convert + fw0 permute (launch idx 1) ----------------
constexpr int PERM_BLOCKS = (H1 * NC + 255) / 256;   // 7296
__global__ void __launch_bounds__(256)
k_prep(const float* __restrict__ fw0, const float* __restrict__ fw1, ConvPtrs cp) {
    int bid = blockIdx.x;
    if (bid < PERM_BLOCKS) {
        int t = bid * 256 + threadIdx.x;
        if (t >= H1 * NC) return;
        int j = t / NC, cc = t - j * NC;
        int ci = 0;
#pragma unroll
        for (int q = 1; q < 7; q++) if (cc >= c_off[q]) ci = q;
        int local = cc - c_off[ci];
        int p = local >> 6, o = local & 63;
        g_fw0h[t] = __float2half_rn(fw0[j * NC + c_off[ci] + o * c_P[ci] + p]);
    } else if (bid < PERM_BLOCKS + 7) {
        int ci = bid - PERM_BLOCKS;
        int o = threadIdx.x;
        if (o >= 64) return;
        int kh = c_kh[ci], kw = c_kw[ci];
        int ks = kh * kw;
        __half* dst = g_Wc + ci * 4096 + o * 64;
        for (int k = 0; k < 64; k++) dst[k] = __half(0.0f);
        const float* w = cp.w[ci] + o * 16 * ks;
        for (int i = 0; i < ks; i++)
            for (int c = 0; c < 16; c++)
                dst[i * 16 + c] = __float2half_rn(w[c * ks + i]);
    } else {
        int i = (bid - PERM_BLOCKS - 7) * 256 + threadIdx.x;
        if (i >= H2 * H1 / 8) return;
        const float4* s = (const float4*)fw1 + 2 * (size_t)i;
        float4 a = s[0], b = s[1];
        __half2 h0 = __floats2half2_rn(a.x, a.y);
        __half2 h1 = __floats2half2_rn(a.z, a.w);
        __half2 h2 = __floats2half2_rn(b.x, b.y);
        __half2 h3 = __floats2half2_rn(b.z, b.w);
        uint4 o;
        o.x = *(uint32_t*)&h0; o.y = *(uint32_t*)&h1;
        o.z = *(uint32_t*)&h2; o.w = *(uint32_t*)&h3;
        ((uint4*)g_fw1h)[i] = o;
    }
}

// ---------------- GEMM helpers ----------------
__device__ __forceinline__ uint32_t swz(uint32_t x) { return x ^ ((x >> 3) & 0x70); }

__device__ __forceinline__ void cp16(uint32_t saddr, const void* g) {
    asm volatile("cp.async.cg.shared.global [%0], [%1], 16;\n" :: "r"(saddr), "l"(g) : "memory");
}
__device__ __forceinline__ void cp_commit() {
    asm volatile("cp.async.commit_group;\n" ::: "memory");
}
template <int N>
__device__ __forceinline__ void cp_wait() {
    asm volatile("cp.async.wait_group %0;\n" :: "n"(N) : "memory");
}

__device__ __forceinline__ void ldsm4(uint32_t& r0, uint32_t& r1, uint32_t& r2, uint32_t& r3,
                                      uint32_t addr) {
    asm volatile("ldmatrix.sync.aligned.m8n8.x4.shared.b16 {%0,%1,%2,%3}, [%4];"
                 : "=r"(r0), "=r"(r1), "=r"(r2), "=r"(r3) : "r"(addr));
}

__device__ __forceinline__ void mma16816(float c[4], const uint32_t a[4], const uint32_t b[2]) {
    asm volatile(
        "mma.sync.aligned.m16n8k16.row.col.f32.f16.f16.f32 "
        "{%0,%1,%2,%3}, {%4,%5,%6,%7}, {%8,%9}, {%0,%1,%2,%3};"
        : "+f"(c[0]), "+f"(c[1]), "+f"(c[2]), "+f"(c[3])
        : "r"(a[0]), "r"(a[1]), "r"(a[2]), "r"(a[3]), "r"(b[0]), "r"(b[1]));
}

// ---------------- direct conv tile (device) — unchanged (R9/R10-passing) ----------------
template <int P, int OW, int KH, int KW>
__device__ __forceinline__ void conv_tile(int tile, int BASE, const __half* __restrict__ wc,
                                          const float* __restrict__ bias) {
    constexpr int NS  = KH * KW;
    constexpr int SMX = 128 / P + 2;

    extern __shared__ char sm[];
    uint32_t sX = (uint32_t)__cvta_generic_to_shared(sm);
    uint32_t sB = (sX + SMX * 544 + 127) & ~127u;
    uint32_t sO = sX;

    const int tid  = threadIdx.x;
    const int lane = tid & 31;
    const int w    = tid >> 5;
    const int wm   = w & 3;
    const int wn   = w >> 2;

    const int R0    = tile * 128;
    const int b0    = R0 / P;
    const int bLast = (R0 + 127) / P;
    const int scnt  = bLast - b0 + 1;

    for (int ch = tid; ch < scnt * 32; ch += 256) {
        int s = ch >> 5, j = ch & 31;
        int pos = j >> 1, hf = j & 1;
        uint32_t off = ((uint32_t)(pos * 32 + hf * 16)) ^ (uint32_t)((pos & 4) << 2);
        cp16(sX + s * 544 + off, g_XP + ((size_t)(b0 + s) << 8) + pos * 16 + hf * 8);
    }
    for (int ch = tid; ch < 512; ch += 256) {
        int row = ch >> 3, cc = ch & 7;
        cp16(sB + swz((uint32_t)(row * 128 + cc * 16)), wc + row * 64 + cc * 8);
    }
    cp_commit();
    cp_wait<0>();
    __syncthreads();

    uint32_t rowaddr[2];
    int wpos0[2];
#pragma unroll
    for (int mt = 0; mt < 2; mt++) {
        int r = R0 + wm * 32 + mt * 16 + (lane & 15);
        int b = r / P, p = r - b * P;
        int py = p / OW, px = p - py * OW;
        rowaddr[mt] = sX + (b - b0) * 544;
        wpos0[mt]   = py * 4 + px;
    }

    float acc[2][4][4];
#pragma unroll
    for (int i = 0; i < 2; i++)
#pragma unroll
        for (int j = 0; j < 4; j++)
#pragma unroll
            for (int q = 0; q < 4; q++) acc[i][j][q] = 0.0f;

#pragma unroll
    for (int i = 0; i < NS; i++) {
        const int D = (i / KW) * 4 + (i % KW);
        uint32_t af[2][4];
#pragma unroll
        for (int mt = 0; mt < 2; mt++) {
            int wp = wpos0[mt] + D;
            uint32_t off = ((uint32_t)(wp * 32 + ((lane >> 4) << 4))) ^ (uint32_t)((wp & 4) << 2);
            ldsm4(af[mt][0], af[mt][1], af[mt][2], af[mt][3], rowaddr[mt] + off);
        }
        uint32_t bf[4][2];
#pragma unroll
        for (int nt2 = 0; nt2 < 2; nt2++) {
            int brow = wn * 32 + nt2 * 16 + ((lane & 16) >> 1) + (lane & 7);
            uint32_t off = swz((uint32_t)(brow * 128 + i * 32 + (((lane >> 3) & 1) << 4)));
            uint32_t r0, r1, r2, r3;
            ldsm4(r0, r1, r2, r3, sB + off);
            bf[nt2 * 2][0] = r0;     bf[nt2 * 2][1] = r1;
            bf[nt2 * 2 + 1][0] = r2; bf[nt2 * 2 + 1][1] = r3;
        }
#pragma unroll
        for (int mt = 0; mt < 2; mt++)
#pragma unroll
            for (int nt = 0; nt < 4; nt++) mma16816(acc[mt][nt], af[mt], bf[nt]);
    }

    __syncthreads();
#pragma unroll
    for (int mt = 0; mt < 2; mt++) {
#pragma unroll
        for (int sub = 0; sub < 2; sub++) {
            int row = wm * 32 + mt * 16 + sub * 8 + (lane >> 2);
#pragma unroll
            for (int nt = 0; nt < 4; nt++) {
                int o = wn * 32 + nt * 8 + ((lane & 3) << 1);
                float2 bb = *(const float2*)(bias + o);
                float v0 = fmaxf(acc[mt][nt][sub * 2 + 0] + bb.x, 0.0f);
                float v1 = fmaxf(acc[mt][nt][sub * 2 + 1] + bb.y, 0.0f);
                __half2 hv = __floats2half2_rn(v0, v1);
                asm volatile("st.shared.b32 [%0], %1;"
                             :: "r"(sO + row * 144 + o * 2), "r"(*(uint32_t*)&hv) : "memory");
            }
        }
    }
    __syncthreads();

    for (int ch = tid; ch < 1024; ch += 256) {
        int row = ch >> 3, w8 = ch & 7;
        int r = R0 + row;
        int b = r / P, p = r - b * P;
        uint4 v;
        asm volatile("ld.shared.v4.u32 {%0,%1,%2,%3}, [%4];"
                     : "=r"(v.x), "=r"(v.y), "=r"(v.z), "=r"(v.w)
                     : "r"(sO + row * 144 + w8 * 16));
        *(uint4*)(g_comb + (size_t)b * NC + BASE + p * 64 + w8 * 8) = v;
    }
}

// single launch for all 7 convs (launch idx 2)
__global__ void __launch_bounds__(256, 3)
conv_all(ConvPtrs cp) {
    int bid = blockIdx.x;
    if (bid < 3072)       conv_tile<12, 3, 1, 2>(bid,         0,    g_Wc,          cp.b[0]);
    else if (bid < 6144)  conv_tile<12, 4, 2, 1>(bid - 3072,  768,  g_Wc + 4096,   cp.b[1]);
    else if (bid < 8192)  conv_tile<8, 2, 1, 3> (bid - 6144,  1536, g_Wc + 8192,   cp.b[2]);
    else if (bid < 10240) conv_tile<8, 4, 3, 1> (bid - 8192,  2048, g_Wc + 12288,  cp.b[3]);
    else if (bid < 11264) conv_tile<4, 1, 1, 4> (bid - 10240, 2560, g_Wc + 16384,  cp.b[4]);
    else if (bid < 12288) conv_tile<4, 4, 4, 1> (bid - 11264, 2816, g_Wc + 20480,  cp.b[5]);
    else                  conv_tile<9, 3, 2, 2> (bid - 12288, 3072, g_Wc + 24576,  cp.b[6]);
}

// ---------------- dense GEMM (NT): 4 warps @ 64x64 each (launch idx 3 — PROFILED) --------
// BM=128, BN=128, BK=64, 3-stage cp.async, 128 threads, 2 CTAs/SM.
// 8 ldsm feed 32 HMMA per warp per ks: 128 B/HMMA smem traffic (was 192).
__global__ void __launch_bounds__(128, 2)
gemm_nt(const __half* __restrict__ A, const __half* __restrict__ Bw,
        const float* __restrict__ bias, __half* __restrict__ C, int N, int K) {
    constexpr int STAGES = 3;
    constexpr int STAGE  = 128 * 128 * 2;
    constexpr int MT = 4, NT = 8;

    extern __shared__ char smemraw[];
    uint32_t sbase = (uint32_t)__cvta_generic_to_shared(smemraw);

    const int tid  = threadIdx.x;
    const int lane = tid & 31;
    const int w    = tid >> 5;       // 0..3
    const int wm   = w & 1;          // 2 strips of 64 rows
    const int wn   = w >> 1;         // 2 strips of 64 cols
    const int bm   = blockIdx.y, bn = blockIdx.x;

    const __half* Ab = A  + (size_t)bm * 128 * K;
    const __half* Bb = Bw + (size_t)bn * 128 * K;
    const int nk = K >> 6;

    float acc[MT][NT][4];
#pragma unroll
    for (int i = 0; i < MT; i++)
#pragma unroll
        for (int j = 0; j < NT; j++)
#pragma unroll
            for (int q = 0; q < 4; q++) acc[i][j][q] = 0.0f;

    auto load_stage = [&](int kt, int s) {
        int k0 = kt << 6;
        uint32_t sA = sbase + s * STAGE;
        uint32_t sB = sA + 128 * 128;
#pragma unroll
        for (int c = tid; c < 128 * 8; c += 128) {
            int row = c >> 3, cc = c & 7;
            cp16(sA + swz((uint32_t)(row * 128 + cc * 16)),
                 Ab + (size_t)row * K + k0 + cc * 8);
        }
#pragma unroll
        for (int c = tid; c < 128 * 8; c += 128) {
            int row = c >> 3, cc = c & 7;
            cp16(sB + swz((uint32_t)(row * 128 + cc * 16)),
                 Bb + (size_t)row * K + k0 + cc * 8);
        }
        cp_commit();
    };

    load_stage(0, 0);
    load_stage(1, 1);

#pragma unroll 1
    for (int kt = 0; kt < nk; ++kt) {
        if (kt == nk - 1) cp_wait<0>(); else cp_wait<1>();
        __syncthreads();
        if (kt + 2 < nk) {
            int s = kt + 2; while (s >= STAGES) s -= STAGES;
            load_stage(kt + 2, s);
        }
        int cs = kt; while (cs >= STAGES) cs -= STAGES;
        uint32_t aT = sbase + cs * STAGE;
        uint32_t bT = aT + 128 * 128;

#pragma unroll
        for (int ks = 0; ks < 4; ++ks) {
            uint32_t af[MT][4];
#pragma unroll
            for (int mt = 0; mt < MT; ++mt) {
                uint32_t off = swz((uint32_t)((wm * 64 + mt * 16 + (lane & 15)) * 128 +
                                              ks * 32 + ((lane >> 4) << 4)));
                ldsm4(af[mt][0], af[mt][1], af[mt][2], af[mt][3], aT + off);
            }
            uint32_t bf[NT][2];
#pragma unroll
            for (int nt2 = 0; nt2 < NT / 2; ++nt2) {
                int brow = wn * 64 + nt2 * 16 + ((lane & 16) >> 1) + (lane & 7);
                uint32_t off = swz((uint32_t)(brow * 128 + ks * 32 + (((lane >> 3) & 1) << 4)));
                uint32_t r0, r1, r2, r3;
                ldsm4(r0, r1, r2, r3, bT + off);
                bf[nt2 * 2][0] = r0;     bf[nt2 * 2][1] = r1;
                bf[nt2 * 2 + 1][0] = r2; bf[nt2 * 2 + 1][1] = r3;
            }
#pragma unroll
            for (int mt = 0; mt < MT; ++mt)
#pragma unroll
                for (int nt = 0; nt < NT; ++nt) mma16816(acc[mt][nt], af[mt], bf[nt]);
        }
    }

#pragma unroll
    for (int mt = 0; mt < MT; ++mt) {
        int r0 = bm * 128 + wm * 64 + mt * 16 + (lane >> 2);
#pragma unroll
        for (int nt = 0; nt < NT; ++nt) {
            int col = bn * 128 + wn * 64 + nt * 8 + ((lane & 3) << 1);
            float2 bb = *(const float2*)(bias + col);
            float v0 = fmaxf(acc[mt][nt][0] + bb.x, 0.0f);
            float v1 = fmaxf(acc[mt][nt][1] + bb.y, 0.0f);
            float v2 = fmaxf(acc[mt][nt][2] + bb.x, 0.0f);
            float v3 = fmaxf(acc[mt][nt][3] + bb.y, 0.0f);
            *(__half2*)(C + (size_t)r0 * N + col)       = __floats2half2_rn(v0, v1);
            *(__half2*)(C + (size_t)(r0 + 8) * N + col) = __floats2half2_rn(v2, v3);
        }
    }
}

// ---------------- GEMM3 fused with final FC (launch idx 4) — unchanged (R10-passing) ----
__global__ void __launch_bounds__(256, 2)
gemm3_fused(const __half* __restrict__ A, const __half* __restrict__ Bw,
            const float* __restrict__ fb1, const float* __restrict__ fw2,
            const float* __restrict__ fb2, float* __restrict__ out) {
    constexpr int STAGES = 3;
    constexpr int STAGE  = 128 * 128 * 2;
    constexpr int MT = 2, NT = 8;
    constexpr int K = H1;
    constexpr int nk = K >> 6;   // 8

    extern __shared__ char smemraw[];
    uint32_t sbase = (uint32_t)__cvta_generic_to_shared(smemraw);

    const int tid  = threadIdx.x;
    const int lane = tid & 31;
    const int w    = tid >> 5;
    const int wm   = w & 3;
    const int wn   = w >> 2;
    const int bm   = blockIdx.y;

    const __half* Ab = A + (size_t)bm * 128 * K;
    const __half* Bb = Bw;

    float acc[MT][NT][4];
#pragma unroll
    for (int i = 0; i < MT; i++)
#pragma unroll
        for (int j = 0; j < NT; j++)
#pragma unroll
            for (int q = 0; q < 4; q++) acc[i][j][q] = 0.0f;

    auto load_stage = [&](int kt, int s) {
        int k0 = kt << 6;
        uint32_t sA = sbase + s * STAGE;
        uint32_t sB = sA + 128 * 128;
#pragma unroll
        for (int c = tid; c < 128 * 8; c += 256) {
            int row = c >> 3, cc = c & 7;
            cp16(sA + swz((uint32_t)(row * 128 + cc * 16)),
                 Ab + (size_t)row * K + k0 + cc * 8);
        }
#pragma unroll
        for (int c = tid; c < 128 * 8; c += 256) {
            int row = c >> 3, cc = c & 7;
            cp16(sB + swz((uint32_t)(row * 128 + cc * 16)),
                 Bb + (size_t)row * K + k0 + cc * 8);
        }
        cp_commit();
    };

    load_stage(0, 0);
    load_stage(1, 1);

#pragma unroll 1
    for (int kt = 0; kt < nk; ++kt) {
        if (kt == nk - 1) cp_wait<0>(); else cp_wait<1>();
        __syncthreads();
        if (kt + 2 < nk) {
            int s = kt + 2; while (s >= STAGES) s -= STAGES;
            load_stage(kt + 2, s);
        }
        int cs = kt; while (cs >= STAGES) cs -= STAGES;
        uint32_t aT = sbase + cs * STAGE;
        uint32_t bT = aT + 128 * 128;

#pragma unroll
        for (int ks = 0; ks < 4; ++ks) {
            uint32_t af[MT][4];
#pragma unroll
            for (int mt = 0; mt < MT; ++mt) {
                uint32_t off = swz((uint32_t)((wm * 32 + mt * 16 + (lane & 15)) * 128 +
                                              ks * 32 + ((lane >> 4) << 4)));
                ldsm4(af[mt][0], af[mt][1], af[mt][2], af[mt][3], aT + off);
            }
            uint32_t bf[NT][2];
#pragma unroll
            for (int nt2 = 0; nt2 < NT / 2; ++nt2) {
                int brow = wn * 64 + nt2 * 16 + ((lane & 16) >> 1) + (lane & 7);
                uint32_t off = swz((uint32_t)(brow * 128 + ks * 32 + (((lane >> 3) & 1) << 4)));
                uint32_t r0, r1, r2, r3;
                ldsm4(r0, r1, r2, r3, bT + off);
                bf[nt2 * 2][0] = r0;     bf[nt2 * 2][1] = r1;
                bf[nt2 * 2 + 1][0] = r2; bf[nt2 * 2 + 1][1] = r3;
            }
#pragma unroll
            for (int mt = 0; mt < MT; ++mt)
#pragma unroll
                for (int nt = 0; nt < NT; ++nt) mma16816(acc[mt][nt], af[mt], bf[nt]);
        }
    }

    __syncthreads();
    float* sfw2 = (float*)smemraw;         // [4][128]
    float* sout = sfw2 + 512;              // [128][4][2]
    for (int i = tid; i < 512; i += 256) sfw2[i] = fw2[i];
    __syncthreads();

#pragma unroll
    for (int mt = 0; mt < MT; ++mt) {
#pragma unroll
        for (int sub = 0; sub < 2; ++sub) {
            float p0 = 0.f, p1 = 0.f, p2 = 0.f, p3 = 0.f;
#pragma unroll
            for (int nt = 0; nt < NT; ++nt) {
                int coll = wn * 64 + nt * 8 + ((lane & 3) << 1);
                float v0 = fmaxf(acc[mt][nt][sub * 2 + 0] + __ldg(fb1 + coll), 0.0f);
                float v1 = fmaxf(acc[mt][nt][sub * 2 + 1] + __ldg(fb1 + coll + 1), 0.0f);
                p0 += v0 * sfw2[0 * 128 + coll] + v1 * sfw2[0 * 128 + coll + 1];
                p1 += v0 * sfw2[1 * 128 + coll] + v1 * sfw2[1 * 128 + coll + 1];
                p2 += v0 * sfw2[2 * 128 + coll] + v1 * sfw2[2 * 128 + coll + 1];
                p3 += v0 * sfw2[3 * 128 + coll] + v1 * sfw2[3 * 128 + coll + 1];
            }
#pragma unroll
            for (int d = 1; d <= 2; d <<= 1) {
                p0 += __shfl_xor_sync(0xffffffffu, p0, d);
                p1 += __shfl_xor_sync(0xffffffffu, p1, d);
                p2 += __shfl_xor_sync(0xffffffffu, p2, d);
                p3 += __shfl_xor_sync(0xffffffffu, p3, d);
            }
            if ((lane & 3) == 0) {
                int row = wm * 32 + mt * 16 + sub * 8 + (lane >> 2);
                sout[(row * 4 + 0) * 2 + wn] = p0;
                sout[(row * 4 + 1) * 2 + wn] = p1;
                sout[(row * 4 + 2) * 2 + wn] = p2;
                sout[(row * 4 + 3) * 2 + wn] = p3;
            }
        }
    }
    __syncthreads();
    for (int i = tid; i < 512; i += 256) {
        int row = i >> 2, j = i & 3;
        out[((size_t)(bm * 128 + row)) * NA + j] = sout[i * 2] + sout[i * 2 + 1] + __ldg(fb2 + j);
    }
}

// ---------------- launch ----------------
extern "C" void kernel_launch(void* const* d_in, const int* in_sizes, int n_in,
                              void* d_out, int out_size) {
    const float* x = (const float*)d_in[0];
    ConvPtrs cp;
    for (int i = 0; i < 7; i++) {
        cp.w[i] = (const float*)d_in[1 + 2 * i];
        cp.b[i] = (const float*)d_in[2 + 2 * i];
    }
    const float* fw0 = (const float*)d_in[15];
    const float* fb0 = (const float*)d_in[16];
    const float* fw1 = (const float*)d_in[17];
    const float* fb1 = (const float*)d_in[18];
    const float* fw2 = (const float*)d_in[19];
    const float* fb2 = (const float*)d_in[20];
    float* out = (float*)d_out;

    constexpr int SMEM_G = 3 * 128 * 128 * 2;  // 98304
    cudaFuncSetAttribute(gemm_nt,     cudaFuncAttributeMaxDynamicSharedMemorySize, SMEM_G);
    cudaFuncSetAttribute(gemm3_fused, cudaFuncAttributeMaxDynamicSharedMemorySize, SMEM_G);

    __half *comb, *fw0h, *h1, *fw1h;
    cudaGetSymbolAddress((void**)&comb, g_comb);
    cudaGetSymbolAddress((void**)&fw0h, g_fw0h);
    cudaGetSymbolAddress((void**)&h1,   g_h1);
    cudaGetSymbolAddress((void**)&fw1h, g_fw1h);

    // idx 0: XP transpose-convert (coalesced)
    k_xp<<<BATCH / 8, 256>>>(x);

    // idx 1: fused weight prep (fw0 permute, conv tiles, fw1 convert)
    k_prep<<<PERM_BLOCKS + 7 + 32, 256>>>(fw0, fw1, cp);

    // idx 2: all 7 convs -> comb
    conv_all<<<14592, 256, 27008>>>(cp);

    // idx 3: GEMM2  h1 = relu(comb * fw0h^T + fb0)   [32768, 512], K=3648  [PROFILED]
    {
        dim3 grid(H1 / 128, BATCH / 128);
        gemm_nt<<<grid, 128, SMEM_G>>>(comb, fw0h, fb0, h1, H1, NC);
    }
    // idx 4: GEMM3 + final FC fused
    {
        dim3 grid(1, BATCH / 128);
        gemm3_fused<<<grid, 256, SMEM_G>>>(h1, fw1h, fb1, fw2, fb2, out);
    }
}

// round 14
// speedup vs baseline: 1.0950x; 1.0505x over previous
#include <cuda_runtime.h>
#include <cuda_fp16.h>
#include <cstdint>

// ---------------- problem constants ----------------
constexpr int BATCH = 32768;
constexpr int NC    = 3648;     // combined features = 57*64 exactly (GEMM2 K)
constexpr int H1    = 512;
constexpr int H2    = 128;
constexpr int NA    = 4;

// ---------------- scratch (device globals; no allocation) ----------------
__device__ __align__(256) __half g_XP  [(size_t)BATCH * 256];     // position-major input
__device__ __align__(256) __half g_Wc  [7 * 64 * 64];             // per-conv weight tiles
__device__ __align__(256) __half g_comb[(size_t)BATCH * NC];      // 227 MB
__device__ __align__(256) __half g_fw0h[(size_t)H1 * NC];         // permuted fc0 weights
__device__ __align__(256) __half g_h1  [(size_t)BATCH * H1];
__device__ __align__(256) __half g_fw1h[(size_t)H2 * H1];

// conv geometry tables
__constant__ int c_off[7] = {0, 768, 1536, 2048, 2560, 2816, 3072};
__constant__ int c_P[7]   = {12, 12, 8, 8, 4, 4, 9};
__constant__ int c_kh[7]  = {1, 2, 1, 3, 1, 4, 2};
__constant__ int c_kw[7]  = {2, 1, 3, 1, 4, 1, 2};

struct ConvPtrs { const float* w[7]; const float* b[7]; };

// ---------------- prep: XP transpose-convert, COALESCED (launch idx 0) ----------------
__global__ void __launch_bounds__(256)
k_xp(const float* __restrict__ x) {
    __shared__ float sx[8][256];
    int s0 = blockIdx.x * 8;
    const float* src = x + (size_t)s0 * 256;
#pragma unroll
    for (int s = 0; s < 8; s++)
        sx[s][threadIdx.x] = src[s * 256 + threadIdx.x];
    __syncthreads();
    int t = threadIdx.x;
    int si = ((t & 15) << 4) | (t >> 4);      // XP[pos*16+c] = x[c*16+pos]
    __half* dst = g_XP + (size_t)s0 * 256;
#pragma unroll
    for (int s = 0; s < 8; s++)
        dst[s * 256 + t] = __float2half_rn(sx[s][si]);
}

// ---------------- prep: fw0 permute (COALESCED, smem transpose) + Wc + fw1 (idx 1) ----
// blocks [0,512): one fw0 row each; [512,519): Wc tiles; [519,551): fw1 convert
__global__ void __launch_bounds__(256)
k_prep_all(const float* __restrict__ fw0, const float* __restrict__ fw1, ConvPtrs cp) {
    int bid = blockIdx.x;
    if (bid < H1) {
        __shared__ float row[NC];
        int j = bid;
        const float* src = fw0 + (size_t)j * NC;
        for (int t = threadIdx.x; t < NC; t += 256) row[t] = src[t];
        __syncthreads();
        __half* dst = g_fw0h + (size_t)j * NC;
        for (int t = threadIdx.x; t < NC; t += 256) {
            int ci = 0;
#pragma unroll
            for (int q = 1; q < 7; q++) if (t >= c_off[q]) ci = q;
            int local = t - c_off[ci];
            int p = local >> 6, o = local & 63;
            dst[t] = __float2half_rn(row[c_off[ci] + o * c_P[ci] + p]);
        }
    } else if (bid < H1 + 7) {
        int ci = bid - H1;
        int o = threadIdx.x;
        if (o >= 64) return;
        int kh = c_kh[ci], kw = c_kw[ci];
        int ks = kh * kw;
        __half* dst = g_Wc + ci * 4096 + o * 64;
        for (int k = 0; k < 64; k++) dst[k] = __half(0.0f);
        const float* w = cp.w[ci] + o * 16 * ks;
        for (int i = 0; i < ks; i++)
            for (int c = 0; c < 16; c++)
                dst[i * 16 + c] = __float2half_rn(w[c * ks + i]);
    } else {
        int i = (bid - H1 - 7) * 256 + threadIdx.x;
        if (i >= H2 * H1 / 8) return;
        const float4* s = (const float4*)fw1 + 2 * (size_t)i;
        float4 a = s[0], b = s[1];
        __half2 h0 = __floats2half2_rn(a.x, a.y);
        __half2 h1 = __floats2half2_rn(a.z, a.w);
        __half2 h2 = __floats2half2_rn(b.x, b.y);
        __half2 h3 = __floats2half2_rn(b.z, b.w);
        uint4 o;
        o.x = *(uint32_t*)&h0; o.y = *(uint32_t*)&h1;
        o.z = *(uint32_t*)&h2; o.w = *(uint32_t*)&h3;
        ((uint4*)g_fw1h)[i] = o;
    }
}

// ---------------- GEMM helpers ----------------
__device__ __forceinline__ uint32_t swz(uint32_t x) { return x ^ ((x >> 3) & 0x70); }

__device__ __forceinline__ void cp16(uint32_t saddr, const void* g) {
    asm volatile("cp.async.cg.shared.global [%0], [%1], 16;\n" :: "r"(saddr), "l"(g) : "memory");
}
__device__ __forceinline__ void cp_commit() {
    asm volatile("cp.async.commit_group;\n" ::: "memory");
}
template <int N>
__device__ __forceinline__ void cp_wait() {
    asm volatile("cp.async.wait_group %0;\n" :: "n"(N) : "memory");
}

__device__ __forceinline__ void ldsm4(uint32_t& r0, uint32_t& r1, uint32_t& r2, uint32_t& r3,
                                      uint32_t addr) {
    asm volatile("ldmatrix.sync.aligned.m8n8.x4.shared.b16 {%0,%1,%2,%3}, [%4];"
                 : "=r"(r0), "=r"(r1), "=r"(r2), "=r"(r3) : "r"(addr));
}

__device__ __forceinline__ void mma16816(float c[4], const uint32_t a[4], const uint32_t b[2]) {
    asm volatile(
        "mma.sync.aligned.m16n8k16.row.col.f32.f16.f16.f32 "
        "{%0,%1,%2,%3}, {%4,%5,%6,%7}, {%8,%9}, {%0,%1,%2,%3};"
        : "+f"(c[0]), "+f"(c[1]), "+f"(c[2]), "+f"(c[3])
        : "r"(a[0]), "r"(a[1]), "r"(a[2]), "r"(a[3]), "r"(b[0]), "r"(b[1]));
}

// ---------------- direct conv tile (device) — unchanged (R9/R10-passing) ----------------
template <int P, int OW, int KH, int KW>
__device__ __forceinline__ void conv_tile(int tile, int BASE, const __half* __restrict__ wc,
                                          const float* __restrict__ bias) {
    constexpr int NS  = KH * KW;
    constexpr int SMX = 128 / P + 2;

    extern __shared__ char sm[];
    uint32_t sX = (uint32_t)__cvta_generic_to_shared(sm);
    uint32_t sB = (sX + SMX * 544 + 127) & ~127u;
    uint32_t sO = sX;

    const int tid  = threadIdx.x;
    const int lane = tid & 31;
    const int w    = tid >> 5;
    const int wm   = w & 3;
    const int wn   = w >> 2;

    const int R0    = tile * 128;
    const int b0    = R0 / P;
    const int bLast = (R0 + 127) / P;
    const int scnt  = bLast - b0 + 1;

    for (int ch = tid; ch < scnt * 32; ch += 256) {
        int s = ch >> 5, j = ch & 31;
        int pos = j >> 1, hf = j & 1;
        uint32_t off = ((uint32_t)(pos * 32 + hf * 16)) ^ (uint32_t)((pos & 4) << 2);
        cp16(sX + s * 544 + off, g_XP + ((size_t)(b0 + s) << 8) + pos * 16 + hf * 8);
    }
    for (int ch = tid; ch < 512; ch += 256) {
        int row = ch >> 3, cc = ch & 7;
        cp16(sB + swz((uint32_t)(row * 128 + cc * 16)), wc + row * 64 + cc * 8);
    }
    cp_commit();
    cp_wait<0>();
    __syncthreads();

    uint32_t rowaddr[2];
    int wpos0[2];
#pragma unroll
    for (int mt = 0; mt < 2; mt++) {
        int r = R0 + wm * 32 + mt * 16 + (lane & 15);
        int b = r / P, p = r - b * P;
        int py = p / OW, px = p - py * OW;
        rowaddr[mt] = sX + (b - b0) * 544;
        wpos0[mt]   = py * 4 + px;
    }

    float acc[2][4][4];
#pragma unroll
    for (int i = 0; i < 2; i++)
#pragma unroll
        for (int j = 0; j < 4; j++)
#pragma unroll
            for (int q = 0; q < 4; q++) acc[i][j][q] = 0.0f;

#pragma unroll
    for (int i = 0; i < NS; i++) {
        const int D = (i / KW) * 4 + (i % KW);
        uint32_t af[2][4];
#pragma unroll
        for (int mt = 0; mt < 2; mt++) {
            int wp = wpos0[mt] + D;
            uint32_t off = ((uint32_t)(wp * 32 + ((lane >> 4) << 4))) ^ (uint32_t)((wp & 4) << 2);
            ldsm4(af[mt][0], af[mt][1], af[mt][2], af[mt][3], rowaddr[mt] + off);
        }
        uint32_t bf[4][2];
#pragma unroll
        for (int nt2 = 0; nt2 < 2; nt2++) {
            int brow = wn * 32 + nt2 * 16 + ((lane & 16) >> 1) + (lane & 7);
            uint32_t off = swz((uint32_t)(brow * 128 + i * 32 + (((lane >> 3) & 1) << 4)));
            uint32_t r0, r1, r2, r3;
            ldsm4(r0, r1, r2, r3, sB + off);
            bf[nt2 * 2][0] = r0;     bf[nt2 * 2][1] = r1;
            bf[nt2 * 2 + 1][0] = r2; bf[nt2 * 2 + 1][1] = r3;
        }
#pragma unroll
        for (int mt = 0; mt < 2; mt++)
#pragma unroll
            for (int nt = 0; nt < 4; nt++) mma16816(acc[mt][nt], af[mt], bf[nt]);
    }

    __syncthreads();
#pragma unroll
    for (int mt = 0; mt < 2; mt++) {
#pragma unroll
        for (int sub = 0; sub < 2; sub++) {
            int row = wm * 32 + mt * 16 + sub * 8 + (lane >> 2);
#pragma unroll
            for (int nt = 0; nt < 4; nt++) {
                int o = wn * 32 + nt * 8 + ((lane & 3) << 1);
                float2 bb = *(const float2*)(bias + o);
                float v0 = fmaxf(acc[mt][nt][sub * 2 + 0] + bb.x, 0.0f);
                float v1 = fmaxf(acc[mt][nt][sub * 2 + 1] + bb.y, 0.0f);
                __half2 hv = __floats2half2_rn(v0, v1);
                asm volatile("st.shared.b32 [%0], %1;"
                             :: "r"(sO + row * 144 + o * 2), "r"(*(uint32_t*)&hv) : "memory");
            }
        }
    }
    __syncthreads();

    for (int ch = tid; ch < 1024; ch += 256) {
        int row = ch >> 3, w8 = ch & 7;
        int r = R0 + row;
        int b = r / P, p = r - b * P;
        uint4 v;
        asm volatile("ld.shared.v4.u32 {%0,%1,%2,%3}, [%4];"
                     : "=r"(v.x), "=r"(v.y), "=r"(v.z), "=r"(v.w)
                     : "r"(sO + row * 144 + w8 * 16));
        *(uint4*)(g_comb + (size_t)b * NC + BASE + p * 64 + w8 * 8) = v;
    }
}

// single launch for all 7 convs (launch idx 2)
__global__ void __launch_bounds__(256, 3)
conv_all(ConvPtrs cp) {
    int bid = blockIdx.x;
    if (bid < 3072)       conv_tile<12, 3, 1, 2>(bid,         0,    g_Wc,          cp.b[0]);
    else if (bid < 6144)  conv_tile<12, 4, 2, 1>(bid - 3072,  768,  g_Wc + 4096,   cp.b[1]);
    else if (bid < 8192)  conv_tile<8, 2, 1, 3> (bid - 6144,  1536, g_Wc + 8192,   cp.b[2]);
    else if (bid < 10240) conv_tile<8, 4, 3, 1> (bid - 8192,  2048, g_Wc + 12288,  cp.b[3]);
    else if (bid < 11264) conv_tile<4, 1, 1, 4> (bid - 10240, 2560, g_Wc + 16384,  cp.b[4]);
    else if (bid < 12288) conv_tile<4, 4, 4, 1> (bid - 11264, 2816, g_Wc + 20480,  cp.b[5]);
    else                  conv_tile<9, 3, 2, 2> (bid - 12288, 3072, g_Wc + 24576,  cp.b[6]);
}

// ---------------- dense GEMM (NT): 4 warps @ 64x64 each (launch idx 3 — PROFILED) --------
// Unchanged from R12 (verified 281.6 us). BM=128, BN=128, BK=64, 3-stage, 128 thr, 2 CTA/SM.
__global__ void __launch_bounds__(128, 2)
gemm_nt(const __half* __restrict__ A, const __half* __restrict__ Bw,
        const float* __restrict__ bias, __half* __restrict__ C, int N, int K) {
    constexpr int STAGES = 3;
    constexpr int STAGE  = 128 * 128 * 2;
    constexpr int MT = 4, NT = 8;

    extern __shared__ char smemraw[];
    uint32_t sbase = (uint32_t)__cvta_generic_to_shared(smemraw);

    const int tid  = threadIdx.x;
    const int lane = tid & 31;
    const int w    = tid >> 5;       // 0..3
    const int wm   = w & 1;          // 2 strips of 64 rows
    const int wn   = w >> 1;         // 2 strips of 64 cols
    const int bm   = blockIdx.y, bn = blockIdx.x;

    const __half* Ab = A  + (size_t)bm * 128 * K;
    const __half* Bb = Bw + (size_t)bn * 128 * K;
    const int nk = K >> 6;

    float acc[MT][NT][4];
#pragma unroll
    for (int i = 0; i < MT; i++)
#pragma unroll
        for (int j = 0; j < NT; j++)
#pragma unroll
            for (int q = 0; q < 4; q++) acc[i][j][q] = 0.0f;

    auto load_stage = [&](int kt, int s) {
        int k0 = kt << 6;
        uint32_t sA = sbase + s * STAGE;
        uint32_t sB = sA + 128 * 128;
#pragma unroll
        for (int c = tid; c < 128 * 8; c += 128) {
            int row = c >> 3, cc = c & 7;
            cp16(sA + swz((uint32_t)(row * 128 + cc * 16)),
                 Ab + (size_t)row * K + k0 + cc * 8);
        }
#pragma unroll
        for (int c = tid; c < 128 * 8; c += 128) {
            int row = c >> 3, cc = c & 7;
            cp16(sB + swz((uint32_t)(row * 128 + cc * 16)),
                 Bb + (size_t)row * K + k0 + cc * 8);
        }
        cp_commit();
    };

    load_stage(0, 0);
    load_stage(1, 1);

#pragma unroll 1
    for (int kt = 0; kt < nk; ++kt) {
        if (kt == nk - 1) cp_wait<0>(); else cp_wait<1>();
        __syncthreads();
        if (kt + 2 < nk) {
            int s = kt + 2; while (s >= STAGES) s -= STAGES;
            load_stage(kt + 2, s);
        }
        int cs = kt; while (cs >= STAGES) cs -= STAGES;
        uint32_t aT = sbase + cs * STAGE;
        uint32_t bT = aT + 128 * 128;

#pragma unroll
        for (int ks = 0; ks < 4; ++ks) {
            uint32_t af[MT][4];
#pragma unroll
            for (int mt = 0; mt < MT; ++mt) {
                uint32_t off = swz((uint32_t)((wm * 64 + mt * 16 + (lane & 15)) * 128 +
                                              ks * 32 + ((lane >> 4) << 4)));
                ldsm4(af[mt][0], af[mt][1], af[mt][2], af[mt][3], aT + off);
            }
            uint32_t bf[NT][2];
#pragma unroll
            for (int nt2 = 0; nt2 < NT / 2; ++nt2) {
                int brow = wn * 64 + nt2 * 16 + ((lane & 16) >> 1) + (lane & 7);
                uint32_t off = swz((uint32_t)(brow * 128 + ks * 32 + (((lane >> 3) & 1) << 4)));
                uint32_t r0, r1, r2, r3;
                ldsm4(r0, r1, r2, r3, bT + off);
                bf[nt2 * 2][0] = r0;     bf[nt2 * 2][1] = r1;
                bf[nt2 * 2 + 1][0] = r2; bf[nt2 * 2 + 1][1] = r3;
            }
#pragma unroll
            for (int mt = 0; mt < MT; ++mt)
#pragma unroll
                for (int nt = 0; nt < NT; ++nt) mma16816(acc[mt][nt], af[mt], bf[nt]);
        }
    }

#pragma unroll
    for (int mt = 0; mt < MT; ++mt) {
        int r0 = bm * 128 + wm * 64 + mt * 16 + (lane >> 2);
#pragma unroll
        for (int nt = 0; nt < NT; ++nt) {
            int col = bn * 128 + wn * 64 + nt * 8 + ((lane & 3) << 1);
            float2 bb = *(const float2*)(bias + col);
            float v0 = fmaxf(acc[mt][nt][0] + bb.x, 0.0f);
            float v1 = fmaxf(acc[mt][nt][1] + bb.y, 0.0f);
            float v2 = fmaxf(acc[mt][nt][2] + bb.x, 0.0f);
            float v3 = fmaxf(acc[mt][nt][3] + bb.y, 0.0f);
            *(__half2*)(C + (size_t)r0 * N + col)       = __floats2half2_rn(v0, v1);
            *(__half2*)(C + (size_t)(r0 + 8) * N + col) = __floats2half2_rn(v2, v3);
        }
    }
}

// ---------------- GEMM3 fused with final FC (launch idx 4) — unchanged (R10-passing) ----
__global__ void __launch_bounds__(256, 2)
gemm3_fused(const __half* __restrict__ A, const __half* __restrict__ Bw,
            const float* __restrict__ fb1, const float* __restrict__ fw2,
            const float* __restrict__ fb2, float* __restrict__ out) {
    constexpr int STAGES = 3;
    constexpr int STAGE  = 128 * 128 * 2;
    constexpr int MT = 2, NT = 8;
    constexpr int K = H1;
    constexpr int nk = K >> 6;   // 8

    extern __shared__ char smemraw[];
    uint32_t sbase = (uint32_t)__cvta_generic_to_shared(smemraw);

    const int tid  = threadIdx.x;
    const int lane = tid & 31;
    const int w    = tid >> 5;
    const int wm   = w & 3;
    const int wn   = w >> 2;
    const int bm   = blockIdx.y;

    const __half* Ab = A + (size_t)bm * 128 * K;
    const __half* Bb = Bw;

    float acc[MT][NT][4];
#pragma unroll
    for (int i = 0; i < MT; i++)
#pragma unroll
        for (int j = 0; j < NT; j++)
#pragma unroll
            for (int q = 0; q < 4; q++) acc[i][j][q] = 0.0f;

    auto load_stage = [&](int kt, int s) {
        int k0 = kt << 6;
        uint32_t sA = sbase + s * STAGE;
        uint32_t sB = sA + 128 * 128;
#pragma unroll
        for (int c = tid; c < 128 * 8; c += 256) {
            int row = c >> 3, cc = c & 7;
            cp16(sA + swz((uint32_t)(row * 128 + cc * 16)),
                 Ab + (size_t)row * K + k0 + cc * 8);
        }
#pragma unroll
        for (int c = tid; c < 128 * 8; c += 256) {
            int row = c >> 3, cc = c & 7;
            cp16(sB + swz((uint32_t)(row * 128 + cc * 16)),
                 Bb + (size_t)row * K + k0 + cc * 8);
        }
        cp_commit();
    };

    load_stage(0, 0);
    load_stage(1, 1);

#pragma unroll 1
    for (int kt = 0; kt < nk; ++kt) {
        if (kt == nk - 1) cp_wait<0>(); else cp_wait<1>();
        __syncthreads();
        if (kt + 2 < nk) {
            int s = kt + 2; while (s >= STAGES) s -= STAGES;
            load_stage(kt + 2, s);
        }
        int cs = kt; while (cs >= STAGES) cs -= STAGES;
        uint32_t aT = sbase + cs * STAGE;
        uint32_t bT = aT + 128 * 128;

#pragma unroll
        for (int ks = 0; ks < 4; ++ks) {
            uint32_t af[MT][4];
#pragma unroll
            for (int mt = 0; mt < MT; ++mt) {
                uint32_t off = swz((uint32_t)((wm * 32 + mt * 16 + (lane & 15)) * 128 +
                                              ks * 32 + ((lane >> 4) << 4)));
                ldsm4(af[mt][0], af[mt][1], af[mt][2], af[mt][3], aT + off);
            }
            uint32_t bf[NT][2];
#pragma unroll
            for (int nt2 = 0; nt2 < NT / 2; ++nt2) {
                int brow = wn * 64 + nt2 * 16 + ((lane & 16) >> 1) + (lane & 7);
                uint32_t off = swz((uint32_t)(brow * 128 + ks * 32 + (((lane >> 3) & 1) << 4)));
                uint32_t r0, r1, r2, r3;
                ldsm4(r0, r1, r2, r3, bT + off);
                bf[nt2 * 2][0] = r0;     bf[nt2 * 2][1] = r1;
                bf[nt2 * 2 + 1][0] = r2; bf[nt2 * 2 + 1][1] = r3;
            }
#pragma unroll
            for (int mt = 0; mt < MT; ++mt)
#pragma unroll
                for (int nt = 0; nt < NT; ++nt) mma16816(acc[mt][nt], af[mt], bf[nt]);
        }
    }

    __syncthreads();
    float* sfw2 = (float*)smemraw;         // [4][128]
    float* sout = sfw2 + 512;              // [128][4][2]
    for (int i = tid; i < 512; i += 256) sfw2[i] = fw2[i];
    __syncthreads();

#pragma unroll
    for (int mt = 0; mt < MT; ++mt) {
#pragma unroll
        for (int sub = 0; sub < 2; ++sub) {
            float p0 = 0.f, p1 = 0.f, p2 = 0.f, p3 = 0.f;
#pragma unroll
            for (int nt = 0; nt < NT; ++nt) {
                int coll = wn * 64 + nt * 8 + ((lane & 3) << 1);
                float v0 = fmaxf(acc[mt][nt][sub * 2 + 0] + __ldg(fb1 + coll), 0.0f);
                float v1 = fmaxf(acc[mt][nt][sub * 2 + 1] + __ldg(fb1 + coll + 1), 0.0f);
                p0 += v0 * sfw2[0 * 128 + coll] + v1 * sfw2[0 * 128 + coll + 1];
                p1 += v0 * sfw2[1 * 128 + coll] + v1 * sfw2[1 * 128 + coll + 1];
                p2 += v0 * sfw2[2 * 128 + coll] + v1 * sfw2[2 * 128 + coll + 1];
                p3 += v0 * sfw2[3 * 128 + coll] + v1 * sfw2[3 * 128 + coll + 1];
            }
#pragma unroll
            for (int d = 1; d <= 2; d <<= 1) {
                p0 += __shfl_xor_sync(0xffffffffu, p0, d);
                p1 += __shfl_xor_sync(0xffffffffu, p1, d);
                p2 += __shfl_xor_sync(0xffffffffu, p2, d);
                p3 += __shfl_xor_sync(0xffffffffu, p3, d);
            }
            if ((lane & 3) == 0) {
                int row = wm * 32 + mt * 16 + sub * 8 + (lane >> 2);
                sout[(row * 4 + 0) * 2 + wn] = p0;
                sout[(row * 4 + 1) * 2 + wn] = p1;
                sout[(row * 4 + 2) * 2 + wn] = p2;
                sout[(row * 4 + 3) * 2 + wn] = p3;
            }
        }
    }
    __syncthreads();
    for (int i = tid; i < 512; i += 256) {
        int row = i >> 2, j = i & 3;
        out[((size_t)(bm * 128 + row)) * NA + j] = sout[i * 2] + sout[i * 2 + 1] + __ldg(fb2 + j);
    }
}

// ---------------- launch ----------------
extern "C" void kernel_launch(void* const* d_in, const int* in_sizes, int n_in,
                              void* d_out, int out_size) {
    const float* x = (const float*)d_in[0];
    ConvPtrs cp;
    for (int i = 0; i < 7; i++) {
        cp.w[i] = (const float*)d_in[1 + 2 * i];
        cp.b[i] = (const float*)d_in[2 + 2 * i];
    }
    const float* fw0 = (const float*)d_in[15];
    const float* fb0 = (const float*)d_in[16];
    const float* fw1 = (const float*)d_in[17];
    const float* fb1 = (const float*)d_in[18];
    const float* fw2 = (const float*)d_in[19];
    const float* fb2 = (const float*)d_in[20];
    float* out = (float*)d_out;

    constexpr int SMEM_G = 3 * 128 * 128 * 2;  // 98304
    cudaFuncSetAttribute(gemm_nt,     cudaFuncAttributeMaxDynamicSharedMemorySize, SMEM_G);
    cudaFuncSetAttribute(gemm3_fused, cudaFuncAttributeMaxDynamicSharedMemorySize, SMEM_G);

    __half *comb, *fw0h, *h1, *fw1h;
    cudaGetSymbolAddress((void**)&comb, g_comb);
    cudaGetSymbolAddress((void**)&fw0h, g_fw0h);
    cudaGetSymbolAddress((void**)&h1,   g_h1);
    cudaGetSymbolAddress((void**)&fw1h, g_fw1h);

    // idx 0: XP transpose-convert (coalesced)
    k_xp<<<BATCH / 8, 256>>>(x);

    // idx 1: ALL weight prep (fw0 coalesced smem-transpose permute, Wc tiles, fw1 cvt)
    k_prep_all<<<H1 + 7 + 32, 256>>>(fw0, fw1, cp);

    // idx 2: all 7 convs -> comb
    conv_all<<<14592, 256, 27008>>>(cp);

    // idx 3: GEMM2  h1 = relu(comb * fw0h^T + fb0)   [32768, 512], K=3648  [PROFILED]
    {
        dim3 grid(H1 / 128, BATCH / 128);
        gemm_nt<<<grid, 128, SMEM_G>>>(comb, fw0h, fb0, h1, H1, NC);
    }
    // idx 4: GEMM3 + final FC fused
    {
        dim3 grid(1, BATCH / 128);
        gemm3_fused<<<grid, 256, SMEM_G>>>(h1, fw1h, fb1, fw2, fb2, out);
    }
}

// round 15
// speedup vs baseline: 1.0989x; 1.0035x over previous
#include <cuda_runtime.h>
#include <cuda_fp16.h>
#include <cstdint>

// ---------------- problem constants ----------------
constexpr int BATCH = 32768;
constexpr int NC    = 3648;     // combined features = 57*64 exactly (GEMM2 K)
constexpr int H1    = 512;
constexpr int H2    = 128;
constexpr int NA    = 4;

// ---------------- scratch (device globals; no allocation) ----------------
__device__ __align__(256) __half g_XP  [(size_t)BATCH * 256];     // position-major input
__device__ __align__(256) __half g_Wc  [7 * 64 * 64];             // per-conv weight tiles
__device__ __align__(256) __half g_comb[(size_t)BATCH * NC];      // 227 MB
__device__ __align__(256) __half g_fw0h[(size_t)H1 * NC];         // permuted fc0 weights
__device__ __align__(256) __half g_h1  [(size_t)BATCH * H1];
__device__ __align__(256) __half g_fw1h[(size_t)H2 * H1];

// conv geometry tables
__constant__ int c_off[7] = {0, 768, 1536, 2048, 2560, 2816, 3072};
__constant__ int c_P[7]   = {12, 12, 8, 8, 4, 4, 9};
__constant__ int c_kh[7]  = {1, 2, 1, 3, 1, 4, 2};
__constant__ int c_kw[7]  = {2, 1, 3, 1, 4, 1, 2};

struct ConvPtrs { const float* w[7]; const float* b[7]; };

// ---------------- prep A: conv weight tiles (launch idx 0) ----------------
__global__ void __launch_bounds__(64)
k_wc(ConvPtrs cp) {
    int ci = blockIdx.x;
    int o = threadIdx.x;
    int kh = c_kh[ci], kw = c_kw[ci];
    int ks = kh * kw;
    __half* dst = g_Wc + ci * 4096 + o * 64;
    for (int k = 0; k < 64; k++) dst[k] = __half(0.0f);
    const float* w = cp.w[ci] + o * 16 * ks;
    for (int i = 0; i < ks; i++)
        for (int c = 0; c < 16; c++)
            dst[i * 16 + c] = __float2half_rn(w[c * ks + i]);
}

// ---------------- prep B: XP transpose-convert, COALESCED (launch idx 1) ----------------
__global__ void __launch_bounds__(256)
k_xp(const float* __restrict__ x) {
    __shared__ float sx[8][256];
    int s0 = blockIdx.x * 8;
    const float* src = x + (size_t)s0 * 256;
#pragma unroll
    for (int s = 0; s < 8; s++)
        sx[s][threadIdx.x] = src[s * 256 + threadIdx.x];
    __syncthreads();
    int t = threadIdx.x;
    int si = ((t & 15) << 4) | (t >> 4);      // XP[pos*16+c] = x[c*16+pos]
    __half* dst = g_XP + (size_t)s0 * 256;
#pragma unroll
    for (int s = 0; s < 8; s++)
        dst[s * 256 + t] = __float2half_rn(sx[s][si]);
}

// ---------------- prep C: fw0 permute (coalesced smem transpose) + fw1 (idx 2) --------
__global__ void __launch_bounds__(256)
k_fw(const float* __restrict__ fw0, const float* __restrict__ fw1) {
    int bid = blockIdx.x;
    if (bid < H1) {
        __shared__ float row[NC];
        int j = bid;
        const float* src = fw0 + (size_t)j * NC;
        for (int t = threadIdx.x; t < NC; t += 256) row[t] = src[t];
        __syncthreads();
        __half* dst = g_fw0h + (size_t)j * NC;
        for (int t = threadIdx.x; t < NC; t += 256) {
            int ci = 0;
#pragma unroll
            for (int q = 1; q < 7; q++) if (t >= c_off[q]) ci = q;
            int local = t - c_off[ci];
            int p = local >> 6, o = local & 63;
            dst[t] = __float2half_rn(row[c_off[ci] + o * c_P[ci] + p]);
        }
    } else {
        int i = (bid - H1) * 256 + threadIdx.x;
        if (i >= H2 * H1 / 8) return;
        const float4* s = (const float4*)fw1 + 2 * (size_t)i;
        float4 a = s[0], b = s[1];
        __half2 h0 = __floats2half2_rn(a.x, a.y);
        __half2 h1 = __floats2half2_rn(a.z, a.w);
        __half2 h2 = __floats2half2_rn(b.x, b.y);
        __half2 h3 = __floats2half2_rn(b.z, b.w);
        uint4 o;
        o.x = *(uint32_t*)&h0; o.y = *(uint32_t*)&h1;
        o.z = *(uint32_t*)&h2; o.w = *(uint32_t*)&h3;
        ((uint4*)g_fw1h)[i] = o;
    }
}

// ---------------- GEMM helpers ----------------
__device__ __forceinline__ uint32_t swz(uint32_t x) { return x ^ ((x >> 3) & 0x70); }

__device__ __forceinline__ void cp16(uint32_t saddr, const void* g) {
    asm volatile("cp.async.cg.shared.global [%0], [%1], 16;\n" :: "r"(saddr), "l"(g) : "memory");
}
__device__ __forceinline__ void cp_commit() {
    asm volatile("cp.async.commit_group;\n" ::: "memory");
}
template <int N>
__device__ __forceinline__ void cp_wait() {
    asm volatile("cp.async.wait_group %0;\n" :: "n"(N) : "memory");
}

__device__ __forceinline__ void ldsm4(uint32_t& r0, uint32_t& r1, uint32_t& r2, uint32_t& r3,
                                      uint32_t addr) {
    asm volatile("ldmatrix.sync.aligned.m8n8.x4.shared.b16 {%0,%1,%2,%3}, [%4];"
                 : "=r"(r0), "=r"(r1), "=r"(r2), "=r"(r3) : "r"(addr));
}

__device__ __forceinline__ void mma16816(float c[4], const uint32_t a[4], const uint32_t b[2]) {
    asm volatile(
        "mma.sync.aligned.m16n8k16.row.col.f32.f16.f16.f32 "
        "{%0,%1,%2,%3}, {%4,%5,%6,%7}, {%8,%9}, {%0,%1,%2,%3};"
        : "+f"(c[0]), "+f"(c[1]), "+f"(c[2]), "+f"(c[3])
        : "r"(a[0]), "r"(a[1]), "r"(a[2]), "r"(a[3]), "r"(b[0]), "r"(b[1]));
}

// ---------------- direct conv tile (device) — same math as R13 ----------------
template <int P, int OW, int KH, int KW>
__device__ __forceinline__ void conv_tile(int tile, int BASE, const __half* __restrict__ wc,
                                          const float* __restrict__ bias) {
    constexpr int NS  = KH * KW;
    constexpr int SMX = 128 / P + 2;

    extern __shared__ char sm[];
    uint32_t sX = (uint32_t)__cvta_generic_to_shared(sm);
    uint32_t sB = (sX + SMX * 544 + 127) & ~127u;
    uint32_t sO = sX;

    const int tid  = threadIdx.x;
    const int lane = tid & 31;
    const int w    = tid >> 5;
    const int wm   = w & 3;
    const int wn   = w >> 2;

    const int R0    = tile * 128;
    const int b0    = R0 / P;
    const int bLast = (R0 + 127) / P;
    const int scnt  = bLast - b0 + 1;

    for (int ch = tid; ch < scnt * 32; ch += 256) {
        int s = ch >> 5, j = ch & 31;
        int pos = j >> 1, hf = j & 1;
        uint32_t off = ((uint32_t)(pos * 32 + hf * 16)) ^ (uint32_t)((pos & 4) << 2);
        cp16(sX + s * 544 + off, g_XP + ((size_t)(b0 + s) << 8) + pos * 16 + hf * 8);
    }
    for (int ch = tid; ch < 512; ch += 256) {
        int row = ch >> 3, cc = ch & 7;
        cp16(sB + swz((uint32_t)(row * 128 + cc * 16)), wc + row * 64 + cc * 8);
    }
    cp_commit();
    cp_wait<0>();
    __syncthreads();

    uint32_t rowaddr[2];
    int wpos0[2];
#pragma unroll
    for (int mt = 0; mt < 2; mt++) {
        int r = R0 + wm * 32 + mt * 16 + (lane & 15);
        int b = r / P, p = r - b * P;
        int py = p / OW, px = p - py * OW;
        rowaddr[mt] = sX + (b - b0) * 544;
        wpos0[mt]   = py * 4 + px;
    }

    float acc[2][4][4];
#pragma unroll
    for (int i = 0; i < 2; i++)
#pragma unroll
        for (int j = 0; j < 4; j++)
#pragma unroll
            for (int q = 0; q < 4; q++) acc[i][j][q] = 0.0f;

#pragma unroll
    for (int i = 0; i < NS; i++) {
        const int D = (i / KW) * 4 + (i % KW);
        uint32_t af[2][4];
#pragma unroll
        for (int mt = 0; mt < 2; mt++) {
            int wp = wpos0[mt] + D;
            uint32_t off = ((uint32_t)(wp * 32 + ((lane >> 4) << 4))) ^ (uint32_t)((wp & 4) << 2);
            ldsm4(af[mt][0], af[mt][1], af[mt][2], af[mt][3], rowaddr[mt] + off);
        }
        uint32_t bf[4][2];
#pragma unroll
        for (int nt2 = 0; nt2 < 2; nt2++) {
            int brow = wn * 32 + nt2 * 16 + ((lane & 16) >> 1) + (lane & 7);
            uint32_t off = swz((uint32_t)(brow * 128 + i * 32 + (((lane >> 3) & 1) << 4)));
            uint32_t r0, r1, r2, r3;
            ldsm4(r0, r1, r2, r3, sB + off);
            bf[nt2 * 2][0] = r0;     bf[nt2 * 2][1] = r1;
            bf[nt2 * 2 + 1][0] = r2; bf[nt2 * 2 + 1][1] = r3;
        }
#pragma unroll
        for (int mt = 0; mt < 2; mt++)
#pragma unroll
            for (int nt = 0; nt < 4; nt++) mma16816(acc[mt][nt], af[mt], bf[nt]);
    }

    __syncthreads();
#pragma unroll
    for (int mt = 0; mt < 2; mt++) {
#pragma unroll
        for (int sub = 0; sub < 2; sub++) {
            int row = wm * 32 + mt * 16 + sub * 8 + (lane >> 2);
#pragma unroll
            for (int nt = 0; nt < 4; nt++) {
                int o = wn * 32 + nt * 8 + ((lane & 3) << 1);
                float2 bb = *(const float2*)(bias + o);
                float v0 = fmaxf(acc[mt][nt][sub * 2 + 0] + bb.x, 0.0f);
                float v1 = fmaxf(acc[mt][nt][sub * 2 + 1] + bb.y, 0.0f);
                __half2 hv = __floats2half2_rn(v0, v1);
                asm volatile("st.shared.b32 [%0], %1;"
                             :: "r"(sO + row * 144 + o * 2), "r"(*(uint32_t*)&hv) : "memory");
            }
        }
    }
    __syncthreads();

    for (int ch = tid; ch < 1024; ch += 256) {
        int row = ch >> 3, w8 = ch & 7;
        int r = R0 + row;
        int b = r / P, p = r - b * P;
        uint4 v;
        asm volatile("ld.shared.v4.u32 {%0,%1,%2,%3}, [%4];"
                     : "=r"(v.x), "=r"(v.y), "=r"(v.z), "=r"(v.w)
                     : "r"(sO + row * 144 + w8 * 16));
        *(uint4*)(g_comb + (size_t)b * NC + BASE + p * 64 + w8 * 8) = v;
    }
}

// single launch for all 7 convs (launch idx 3 — PROFILED); occupancy 3 -> 4
__global__ void __launch_bounds__(256, 4)
conv_all(ConvPtrs cp) {
    int bid = blockIdx.x;
    if (bid < 3072)       conv_tile<12, 3, 1, 2>(bid,         0,    g_Wc,          cp.b[0]);
    else if (bid < 6144)  conv_tile<12, 4, 2, 1>(bid - 3072,  768,  g_Wc + 4096,   cp.b[1]);
    else if (bid < 8192)  conv_tile<8, 2, 1, 3> (bid - 6144,  1536, g_Wc + 8192,   cp.b[2]);
    else if (bid < 10240) conv_tile<8, 4, 3, 1> (bid - 8192,  2048, g_Wc + 12288,  cp.b[3]);
    else if (bid < 11264) conv_tile<4, 1, 1, 4> (bid - 10240, 2560, g_Wc + 16384,  cp.b[4]);
    else if (bid < 12288) conv_tile<4, 4, 4, 1> (bid - 11264, 2816, g_Wc + 20480,  cp.b[5]);
    else                  conv_tile<9, 3, 2, 2> (bid - 12288, 3072, g_Wc + 24576,  cp.b[6]);
}

// ---------------- dense GEMM (NT): 4 warps @ 64x64 (launch idx 4) — R12/R13-verified ----
__global__ void __launch_bounds__(128, 2)
gemm_nt(const __half* __restrict__ A, const __half* __restrict__ Bw,
        const float* __restrict__ bias, __half* __restrict__ C, int N, int K) {
    constexpr int STAGES = 3;
    constexpr int STAGE  = 128 * 128 * 2;
    constexpr int MT = 4, NT = 8;

    extern __shared__ char smemraw[];
    uint32_t sbase = (uint32_t)__cvta_generic_to_shared(smemraw);

    const int tid  = threadIdx.x;
    const int lane = tid & 31;
    const int w    = tid >> 5;
    const int wm   = w & 1;
    const int wn   = w >> 1;
    const int bm   = blockIdx.y, bn = blockIdx.x;

    const __half* Ab = A  + (size_t)bm * 128 * K;
    const __half* Bb = Bw + (size_t)bn * 128 * K;
    const int nk = K >> 6;

    float acc[MT][NT][4];
#pragma unroll
    for (int i = 0; i < MT; i++)
#pragma unroll
        for (int j = 0; j < NT; j++)
#pragma unroll
            for (int q = 0; q < 4; q++) acc[i][j][q] = 0.0f;

    auto load_stage = [&](int kt, int s) {
        int k0 = kt << 6;
        uint32_t sA = sbase + s * STAGE;
        uint32_t sB = sA + 128 * 128;
#pragma unroll
        for (int c = tid; c < 128 * 8; c += 128) {
            int row = c >> 3, cc = c & 7;
            cp16(sA + swz((uint32_t)(row * 128 + cc * 16)),
                 Ab + (size_t)row * K + k0 + cc * 8);
        }
#pragma unroll
        for (int c = tid; c < 128 * 8; c += 128) {
            int row = c >> 3, cc = c & 7;
            cp16(sB + swz((uint32_t)(row * 128 + cc * 16)),
                 Bb + (size_t)row * K + k0 + cc * 8);
        }
        cp_commit();
    };

    load_stage(0, 0);
    load_stage(1, 1);

#pragma unroll 1
    for (int kt = 0; kt < nk; ++kt) {
        if (kt == nk - 1) cp_wait<0>(); else cp_wait<1>();
        __syncthreads();
        if (kt + 2 < nk) {
            int s = kt + 2; while (s >= STAGES) s -= STAGES;
            load_stage(kt + 2, s);
        }
        int cs = kt; while (cs >= STAGES) cs -= STAGES;
        uint32_t aT = sbase + cs * STAGE;
        uint32_t bT = aT + 128 * 128;

#pragma unroll
        for (int ks = 0; ks < 4; ++ks) {
            uint32_t af[MT][4];
#pragma unroll
            for (int mt = 0; mt < MT; ++mt) {
                uint32_t off = swz((uint32_t)((wm * 64 + mt * 16 + (lane & 15)) * 128 +
                                              ks * 32 + ((lane >> 4) << 4)));
                ldsm4(af[mt][0], af[mt][1], af[mt][2], af[mt][3], aT + off);
            }
            uint32_t bf[NT][2];
#pragma unroll
            for (int nt2 = 0; nt2 < NT / 2; ++nt2) {
                int brow = wn * 64 + nt2 * 16 + ((lane & 16) >> 1) + (lane & 7);
                uint32_t off = swz((uint32_t)(brow * 128 + ks * 32 + (((lane >> 3) & 1) << 4)));
                uint32_t r0, r1, r2, r3;
                ldsm4(r0, r1, r2, r3, bT + off);
                bf[nt2 * 2][0] = r0;     bf[nt2 * 2][1] = r1;
                bf[nt2 * 2 + 1][0] = r2; bf[nt2 * 2 + 1][1] = r3;
            }
#pragma unroll
            for (int mt = 0; mt < MT; ++mt)
#pragma unroll
                for (int nt = 0; nt < NT; ++nt) mma16816(acc[mt][nt], af[mt], bf[nt]);
        }
    }

#pragma unroll
    for (int mt = 0; mt < MT; ++mt) {
        int r0 = bm * 128 + wm * 64 + mt * 16 + (lane >> 2);
#pragma unroll
        for (int nt = 0; nt < NT; ++nt) {
            int col = bn * 128 + wn * 64 + nt * 8 + ((lane & 3) << 1);
            float2 bb = *(const float2*)(bias + col);
            float v0 = fmaxf(acc[mt][nt][0] + bb.x, 0.0f);
            float v1 = fmaxf(acc[mt][nt][1] + bb.y, 0.0f);
            float v2 = fmaxf(acc[mt][nt][2] + bb.x, 0.0f);
            float v3 = fmaxf(acc[mt][nt][3] + bb.y, 0.0f);
            *(__half2*)(C + (size_t)r0 * N + col)       = __floats2half2_rn(v0, v1);
            *(__half2*)(C + (size_t)(r0 + 8) * N + col) = __floats2half2_rn(v2, v3);
        }
    }
}

// ---------------- GEMM3 fused with final FC (launch idx 5) — unchanged ----------------
__global__ void __launch_bounds__(256, 2)
gemm3_fused(const __half* __restrict__ A, const __half* __restrict__ Bw,
            const float* __restrict__ fb1, const float* __restrict__ fw2,
            const float* __restrict__ fb2, float* __restrict__ out) {
    constexpr int STAGES = 3;
    constexpr int STAGE  = 128 * 128 * 2;
    constexpr int MT = 2, NT = 8;
    constexpr int K = H1;
    constexpr int nk = K >> 6;   // 8

    extern __shared__ char smemraw[];
    uint32_t sbase = (uint32_t)__cvta_generic_to_shared(smemraw);

    const int tid  = threadIdx.x;
    const int lane = tid & 31;
    const int w    = tid >> 5;
    const int wm   = w & 3;
    const int wn   = w >> 2;
    const int bm   = blockIdx.y;

    const __half* Ab = A + (size_t)bm * 128 * K;
    const __half* Bb = Bw;

    float acc[MT][NT][4];
#pragma unroll
    for (int i = 0; i < MT; i++)
#pragma unroll
        for (int j = 0; j < NT; j++)
#pragma unroll
            for (int q = 0; q < 4; q++) acc[i][j][q] = 0.0f;

    auto load_stage = [&](int kt, int s) {
        int k0 = kt << 6;
        uint32_t sA = sbase + s * STAGE;
        uint32_t sB = sA + 128 * 128;
#pragma unroll
        for (int c = tid; c < 128 * 8; c += 256) {
            int row = c >> 3, cc = c & 7;
            cp16(sA + swz((uint32_t)(row * 128 + cc * 16)),
                 Ab + (size_t)row * K + k0 + cc * 8);
        }
#pragma unroll
        for (int c = tid; c < 128 * 8; c += 256) {
            int row = c >> 3, cc = c & 7;
            cp16(sB + swz((uint32_t)(row * 128 + cc * 16)),
                 Bb + (size_t)row * K + k0 + cc * 8);
        }
        cp_commit();
    };

    load_stage(0, 0);
    load_stage(1, 1);

#pragma unroll 1
    for (int kt = 0; kt < nk; ++kt) {
        if (kt == nk - 1) cp_wait<0>(); else cp_wait<1>();
        __syncthreads();
        if (kt + 2 < nk) {
            int s = kt + 2; while (s >= STAGES) s -= STAGES;
            load_stage(kt + 2, s);
        }
        int cs = kt; while (cs >= STAGES) cs -= STAGES;
        uint32_t aT = sbase + cs * STAGE;
        uint32_t bT = aT + 128 * 128;

#pragma unroll
        for (int ks = 0; ks < 4; ++ks) {
            uint32_t af[MT][4];
#pragma unroll
            for (int mt = 0; mt < MT; ++mt) {
                uint32_t off = swz((uint32_t)((wm * 32 + mt * 16 + (lane & 15)) * 128 +
                                              ks * 32 + ((lane >> 4) << 4)));
                ldsm4(af[mt][0], af[mt][1], af[mt][2], af[mt][3], aT + off);
            }
            uint32_t bf[NT][2];
#pragma unroll
            for (int nt2 = 0; nt2 < NT / 2; ++nt2) {
                int brow = wn * 64 + nt2 * 16 + ((lane & 16) >> 1) + (lane & 7);
                uint32_t off = swz((uint32_t)(brow * 128 + ks * 32 + (((lane >> 3) & 1) << 4)));
                uint32_t r0, r1, r2, r3;
                ldsm4(r0, r1, r2, r3, bT + off);
                bf[nt2 * 2][0] = r0;     bf[nt2 * 2][1] = r1;
                bf[nt2 * 2 + 1][0] = r2; bf[nt2 * 2 + 1][1] = r3;
            }
#pragma unroll
            for (int mt = 0; mt < MT; ++mt)
#pragma unroll
                for (int nt = 0; nt < NT; ++nt) mma16816(acc[mt][nt], af[mt], bf[nt]);
        }
    }

    __syncthreads();
    float* sfw2 = (float*)smemraw;         // [4][128]
    float* sout = sfw2 + 512;              // [128][4][2]
    for (int i = tid; i < 512; i += 256) sfw2[i] = fw2[i];
    __syncthreads();

#pragma unroll
    for (int mt = 0; mt < MT; ++mt) {
#pragma unroll
        for (int sub = 0; sub < 2; ++sub) {
            float p0 = 0.f, p1 = 0.f, p2 = 0.f, p3 = 0.f;
#pragma unroll
            for (int nt = 0; nt < NT; ++nt) {
                int coll = wn * 64 + nt * 8 + ((lane & 3) << 1);
                float v0 = fmaxf(acc[mt][nt][sub * 2 + 0] + __ldg(fb1 + coll), 0.0f);
                float v1 = fmaxf(acc[mt][nt][sub * 2 + 1] + __ldg(fb1 + coll + 1), 0.0f);
                p0 += v0 * sfw2[0 * 128 + coll] + v1 * sfw2[0 * 128 + coll + 1];
                p1 += v0 * sfw2[1 * 128 + coll] + v1 * sfw2[1 * 128 + coll + 1];
                p2 += v0 * sfw2[2 * 128 + coll] + v1 * sfw2[2 * 128 + coll + 1];
                p3 += v0 * sfw2[3 * 128 + coll] + v1 * sfw2[3 * 128 + coll + 1];
            }
#pragma unroll
            for (int d = 1; d <= 2; d <<= 1) {
                p0 += __shfl_xor_sync(0xffffffffu, p0, d);
                p1 += __shfl_xor_sync(0xffffffffu, p1, d);
                p2 += __shfl_xor_sync(0xffffffffu, p2, d);
                p3 += __shfl_xor_sync(0xffffffffu, p3, d);
            }
            if ((lane & 3) == 0) {
                int row = wm * 32 + mt * 16 + sub * 8 + (lane >> 2);
                sout[(row * 4 + 0) * 2 + wn] = p0;
                sout[(row * 4 + 1) * 2 + wn] = p1;
                sout[(row * 4 + 2) * 2 + wn] = p2;
                sout[(row * 4 + 3) * 2 + wn] = p3;
            }
        }
    }
    __syncthreads();
    for (int i = tid; i < 512; i += 256) {
        int row = i >> 2, j = i & 3;
        out[((size_t)(bm * 128 + row)) * NA + j] = sout[i * 2] + sout[i * 2 + 1] + __ldg(fb2 + j);
    }
}

// ---------------- launch ----------------
extern "C" void kernel_launch(void* const* d_in, const int* in_sizes, int n_in,
                              void* d_out, int out_size) {
    const float* x = (const float*)d_in[0];
    ConvPtrs cp;
    for (int i = 0; i < 7; i++) {
        cp.w[i] = (const float*)d_in[1 + 2 * i];
        cp.b[i] = (const float*)d_in[2 + 2 * i];
    }
    const float* fw0 = (const float*)d_in[15];
    const float* fb0 = (const float*)d_in[16];
    const float* fw1 = (const float*)d_in[17];
    const float* fb1 = (const float*)d_in[18];
    const float* fw2 = (const float*)d_in[19];
    const float* fb2 = (const float*)d_in[20];
    float* out = (float*)d_out;

    constexpr int SMEM_G = 3 * 128 * 128 * 2;  // 98304
    cudaFuncSetAttribute(gemm_nt,     cudaFuncAttributeMaxDynamicSharedMemorySize, SMEM_G);
    cudaFuncSetAttribute(gemm3_fused, cudaFuncAttributeMaxDynamicSharedMemorySize, SMEM_G);

    __half *comb, *fw0h, *h1, *fw1h;
    cudaGetSymbolAddress((void**)&comb, g_comb);
    cudaGetSymbolAddress((void**)&fw0h, g_fw0h);
    cudaGetSymbolAddress((void**)&h1,   g_h1);
    cudaGetSymbolAddress((void**)&fw1h, g_fw1h);

    // idx 0: conv weight tiles
    k_wc<<<7, 64>>>(cp);

    // idx 1: XP transpose-convert (coalesced)
    k_xp<<<BATCH / 8, 256>>>(x);

    // idx 2: fw0 permute + fw1 convert
    k_fw<<<H1 + 32, 256>>>(fw0, fw1);

    // idx 3: all 7 convs -> comb   [PROFILED]
    conv_all<<<14592, 256, 27008>>>(cp);

    // idx 4: GEMM2  h1 = relu(comb * fw0h^T + fb0)   [32768, 512], K=3648
    {
        dim3 grid(H1 / 128, BATCH / 128);
        gemm_nt<<<grid, 128, SMEM_G>>>(comb, fw0h, fb0, h1, H1, NC);
    }
    // idx 5: GEMM3 + final FC fused
    {
        dim3 grid(1, BATCH / 128);
        gemm3_fused<<<grid, 256, SMEM_G>>>(h1, fw1h, fb1, fw2, fb2, out);
    }
}